// round 1
// baseline (speedup 1.0000x reference)
#include <cuda_runtime.h>
#include <math.h>

#define BATCH 2
#define SEQ 2048
#define DIM 1024
#define NH 16
#define HD 64
#define DH 32              // half head dim
#define MTOT (BATCH*SEQ)   // 4096
#define SCALE 0.125f       // 1/sqrt(64)

// Scratch (device globals; no allocation allowed)
__device__ float g_Q[BATCH*NH*SEQ*HD];
__device__ float g_K[BATCH*NH*SEQ*HD];
__device__ float g_V[BATCH*NH*SEQ*HD];
__device__ float g_sin[SEQ*DH];
__device__ float g_cos[SEQ*DH];

// ---------------------------------------------------------------------------
// RoPE tables in double precision (safe vs fast-math sinf at large angles)
// ---------------------------------------------------------------------------
__global__ void rope_table_kernel() {
    int idx = blockIdx.x * blockDim.x + threadIdx.x;
    if (idx >= SEQ * DH) return;
    int s = idx / DH, i = idx % DH;
    double ang = (double)s * pow(10000.0, -((double)i) / (double)DH);
    g_sin[idx] = (float)sin(ang);
    g_cos[idx] = (float)cos(ang);
}

// ---------------------------------------------------------------------------
// Projection: Y = X @ W^T + b, reshaped to [B,H,S,HD], optional RoPE.
// Tile: 64x64 output, K-step 16, 256 threads, 4x4 micro-tile per thread.
// which: 0 -> g_Q (rope), 1 -> g_K (rope), 2 -> g_V (no rope)
// ---------------------------------------------------------------------------
__global__ __launch_bounds__(256) void proj_kernel(
    const float* __restrict__ X, const float* __restrict__ W,
    const float* __restrict__ bias, int which)
{
    __shared__ float Ash[16][65];
    __shared__ float Bsh[16][65];
    __shared__ float Ysh[64][65];

    float* outp = (which == 0) ? g_Q : (which == 1) ? g_K : g_V;
    const int apply_rope = (which != 2);

    int tid = threadIdx.x;
    int n0 = blockIdx.x * 64;   // output feature tile (one full head)
    int m0 = blockIdx.y * 64;   // row tile (within one batch; 2048 % 64 == 0)
    int ti = tid >> 4, tj = tid & 15;

    float acc[4][4] = {};

    for (int k0 = 0; k0 < DIM; k0 += 16) {
        #pragma unroll
        for (int i = 0; i < 4; i++) {
            int idx = tid + i * 256;
            int r = idx >> 4, c = idx & 15;
            Ash[c][r] = X[(m0 + r) * DIM + k0 + c];
            Bsh[c][r] = W[(n0 + r) * DIM + k0 + c];
        }
        __syncthreads();
        #pragma unroll
        for (int c = 0; c < 16; c++) {
            float a[4], bb[4];
            #pragma unroll
            for (int i = 0; i < 4; i++) a[i] = Ash[c][ti * 4 + i];
            #pragma unroll
            for (int j = 0; j < 4; j++) bb[j] = Bsh[c][tj * 4 + j];
            #pragma unroll
            for (int i = 0; i < 4; i++)
                #pragma unroll
                for (int j = 0; j < 4; j++)
                    acc[i][j] += a[i] * bb[j];
        }
        __syncthreads();
    }

    #pragma unroll
    for (int i = 0; i < 4; i++)
        #pragma unroll
        for (int j = 0; j < 4; j++)
            Ysh[ti * 4 + i][tj * 4 + j] = acc[i][j] + bias[n0 + tj * 4 + j];
    __syncthreads();

    int h = n0 / HD;
    int b = m0 / SEQ;
    #pragma unroll
    for (int i = 0; i < 16; i++) {
        int idx = tid + i * 256;
        int r = idx >> 6, c = idx & 63;
        int s = (m0 + r) % SEQ;
        float val;
        if (apply_rope) {
            if (c < DH) {
                float x1 = Ysh[r][c], x2 = Ysh[r][c + DH];
                val = x1 * g_cos[s * DH + c] - x2 * g_sin[s * DH + c];
            } else {
                int c2 = c - DH;
                float x1 = Ysh[r][c2], x2 = Ysh[r][c];
                val = x1 * g_sin[s * DH + c2] + x2 * g_cos[s * DH + c2];
            }
        } else {
            val = Ysh[r][c];
        }
        outp[(((b * NH + h) * SEQ) + s) * HD + c] = val;
    }
}

// ---------------------------------------------------------------------------
// Flash attention: 64 queries x full K sweep in 64-key tiles.
// grid = (SEQ/64, BATCH*NH), block = 256 threads, 4x4 micro-tiles.
// ---------------------------------------------------------------------------
__global__ __launch_bounds__(256) void attn_kernel(float* __restrict__ out) {
    extern __shared__ float sm[];
    float* q_sh = sm;                 // 64*65
    float* k_sh = q_sh + 64 * 65;     // 64*65
    float* v_sh = k_sh + 64 * 65;     // 64*65
    float* s_sh = v_sh + 64 * 65;     // 64*65
    float* m_sh = s_sh + 64 * 65;     // 64
    float* l_sh = m_sh + 64;          // 64
    float* al_sh = l_sh + 64;         // 64

    int tid = threadIdx.x;
    int q0 = blockIdx.x * 64;
    int bh = blockIdx.y;
    int b = bh / NH, h = bh % NH;

    const float* Qb = g_Q + (size_t)bh * SEQ * HD;
    const float* Kb = g_K + (size_t)bh * SEQ * HD;
    const float* Vb = g_V + (size_t)bh * SEQ * HD;

    #pragma unroll
    for (int i = 0; i < 16; i++) {
        int idx = tid + i * 256;
        int r = idx >> 6, c = idx & 63;
        q_sh[r * 65 + c] = Qb[(q0 + r) * HD + c];
    }
    if (tid < 64) { m_sh[tid] = -INFINITY; l_sh[tid] = 0.f; }

    int ti = tid >> 4, tj = tid & 15;
    float acc[4][4] = {};

    for (int kt = 0; kt < SEQ / 64; kt++) {
        __syncthreads();  // covers q/m/l init on first iter; k/v/s reuse after
        #pragma unroll
        for (int i = 0; i < 16; i++) {
            int idx = tid + i * 256;
            int r = idx >> 6, c = idx & 63;
            k_sh[r * 65 + c] = Kb[(kt * 64 + r) * HD + c];
            v_sh[r * 65 + c] = Vb[(kt * 64 + r) * HD + c];
        }
        __syncthreads();

        // scores: s[i][j] = q[i] . k[j]
        float sc[4][4] = {};
        #pragma unroll 8
        for (int d = 0; d < 64; d++) {
            float a[4], bb[4];
            #pragma unroll
            for (int i = 0; i < 4; i++) a[i] = q_sh[(ti * 4 + i) * 65 + d];
            #pragma unroll
            for (int j = 0; j < 4; j++) bb[j] = k_sh[(tj * 4 + j) * 65 + d];
            #pragma unroll
            for (int i = 0; i < 4; i++)
                #pragma unroll
                for (int j = 0; j < 4; j++)
                    sc[i][j] += a[i] * bb[j];
        }
        #pragma unroll
        for (int i = 0; i < 4; i++)
            #pragma unroll
            for (int j = 0; j < 4; j++)
                s_sh[(ti * 4 + i) * 65 + tj * 4 + j] = sc[i][j] * SCALE;
        __syncthreads();

        // online softmax row pass: 4 threads per row
        {
            int r = tid >> 2, g = tid & 3;
            float* row = s_sh + r * 65 + g * 16;
            float mx = -INFINITY;
            #pragma unroll
            for (int j = 0; j < 16; j++) mx = fmaxf(mx, row[j]);
            mx = fmaxf(mx, __shfl_xor_sync(0xffffffffu, mx, 1));
            mx = fmaxf(mx, __shfl_xor_sync(0xffffffffu, mx, 2));
            float m_old = m_sh[r];
            float m_new = fmaxf(m_old, mx);
            float alpha = expf(m_old - m_new);  // exp(-inf)=0 on first tile
            float sum = 0.f;
            #pragma unroll
            for (int j = 0; j < 16; j++) {
                float p = expf(row[j] - m_new);
                row[j] = p;
                sum += p;
            }
            sum += __shfl_xor_sync(0xffffffffu, sum, 1);
            sum += __shfl_xor_sync(0xffffffffu, sum, 2);
            __syncwarp();
            if (g == 0) {
                m_sh[r] = m_new;
                l_sh[r] = l_sh[r] * alpha + sum;
                al_sh[r] = alpha;
            }
        }
        __syncthreads();

        // rescale accumulators, then acc += P @ V
        float alp[4];
        #pragma unroll
        for (int i = 0; i < 4; i++) alp[i] = al_sh[ti * 4 + i];
        #pragma unroll
        for (int i = 0; i < 4; i++)
            #pragma unroll
            for (int j = 0; j < 4; j++)
                acc[i][j] *= alp[i];
        #pragma unroll 8
        for (int jj = 0; jj < 64; jj++) {
            float p[4], vv[4];
            #pragma unroll
            for (int i = 0; i < 4; i++) p[i] = s_sh[(ti * 4 + i) * 65 + jj];
            #pragma unroll
            for (int j = 0; j < 4; j++) vv[j] = v_sh[jj * 65 + tj * 4 + j];
            #pragma unroll
            for (int i = 0; i < 4; i++)
                #pragma unroll
                for (int j = 0; j < 4; j++)
                    acc[i][j] += p[i] * vv[j];
        }
    }
    __syncthreads();

    float linv[4];
    #pragma unroll
    for (int i = 0; i < 4; i++) linv[i] = 1.f / l_sh[ti * 4 + i];
    #pragma unroll
    for (int i = 0; i < 4; i++) {
        int s = q0 + ti * 4 + i;
        #pragma unroll
        for (int j = 0; j < 4; j++)
            out[((size_t)b * SEQ + s) * DIM + h * HD + tj * 4 + j] = acc[i][j] * linv[i];
    }
}

// ---------------------------------------------------------------------------
extern "C" void kernel_launch(void* const* d_in, const int* in_sizes, int n_in,
                              void* d_out, int out_size) {
    const float* X  = (const float*)d_in[0];
    const float* Wq = (const float*)d_in[1];
    const float* bq = (const float*)d_in[2];
    const float* Wk = (const float*)d_in[3];
    const float* bk = (const float*)d_in[4];
    const float* Wv = (const float*)d_in[5];
    const float* bv = (const float*)d_in[6];
    float* out = (float*)d_out;

    rope_table_kernel<<<(SEQ * DH + 255) / 256, 256>>>();

    dim3 pgrid(DIM / 64, MTOT / 64);
    proj_kernel<<<pgrid, 256>>>(X, Wq, bq, 0);
    proj_kernel<<<pgrid, 256>>>(X, Wk, bk, 1);
    proj_kernel<<<pgrid, 256>>>(X, Wv, bv, 2);

    int smem = (4 * 64 * 65 + 3 * 64) * (int)sizeof(float);
    cudaFuncSetAttribute(attn_kernel, cudaFuncAttributeMaxDynamicSharedMemorySize, smem);
    dim3 agrid(SEQ / 64, BATCH * NH);
    attn_kernel<<<agrid, 256, smem>>>(out);
}

// round 5
// speedup vs baseline: 1.4948x; 1.4948x over previous
#include <cuda_runtime.h>
#include <cuda_bf16.h>
#include <mma.h>
#include <math.h>
#include <stdint.h>

using namespace nvcuda;

#define BATCH 2
#define SEQ 2048
#define DIM 1024
#define NH 16
#define HD 64
#define DH 32
#define MTOT (BATCH*SEQ)   // 4096
#define SCALE 0.125f

// ---------------- device scratch (no allocation allowed) -------------------
__device__ float g_Q[MTOT*DIM];
__device__ float g_K[MTOT*DIM];
__device__ float g_V[MTOT*DIM];
__device__ float g_Y[3][MTOT*DIM];
__device__ float g_sin[SEQ*DH], g_cos[SEQ*DH];
__device__ __nv_bfloat16 g_Xhi[MTOT*DIM], g_Xlo[MTOT*DIM];
__device__ __nv_bfloat16 g_Whi[3][DIM*DIM], g_Wlo[3][DIM*DIM];

// ---------------------------------------------------------------------------
// RoPE tables in double precision (safe at large angles)
// ---------------------------------------------------------------------------
__global__ void rope_table_kernel() {
    int idx = blockIdx.x * blockDim.x + threadIdx.x;
    if (idx >= SEQ * DH) return;
    int s = idx / DH, i = idx % DH;
    double ang = (double)s * pow(10000.0, -((double)i) / (double)DH);
    g_sin[idx] = (float)sin(ang);
    g_cos[idx] = (float)cos(ang);
}

// ---------------------------------------------------------------------------
// Split fp32 -> bf16 hi + bf16 lo.  which: 0=X, 1..3=W[0..2]
// ---------------------------------------------------------------------------
__global__ void split_kernel(const float* __restrict__ src, int which, int n2) {
    __nv_bfloat16* hi = (which == 0) ? g_Xhi : g_Whi[which - 1];
    __nv_bfloat16* lo = (which == 0) ? g_Xlo : g_Wlo[which - 1];
    int i = blockIdx.x * blockDim.x + threadIdx.x;
    if (i >= n2) return;
    float2 x = ((const float2*)src)[i];
    float h0 = __bfloat162float(__float2bfloat16(x.x));
    float h1 = __bfloat162float(__float2bfloat16(x.y));
    __nv_bfloat162 hh, ll;
    hh.x = __float2bfloat16(h0);
    hh.y = __float2bfloat16(h1);
    ll.x = __float2bfloat16(x.x - h0);
    ll.y = __float2bfloat16(x.y - h1);
    ((__nv_bfloat162*)hi)[i] = hh;
    ((__nv_bfloat162*)lo)[i] = ll;
}

// ---------------------------------------------------------------------------
// Pure WMMA GEMM: g_Y[which] = X @ W[which]^T  (bf16 hi/lo split, 3 MMAs).
// Tile 128x128, 8 warps (2m x 4n), k-chunk 32. Accumulators stored DIRECTLY
// to global fp32 (no smem overlay, no fused epilogue).
// ---------------------------------------------------------------------------
#define PLD 40      // bf16 smem ld
#define PROJ_SMEM (4 * 128 * PLD * 2)   // 40960 bytes

__global__ __launch_bounds__(256) void gemm_wmma() {
    extern __shared__ __align__(128) char smraw[];
    __nv_bfloat16* Ahi = (__nv_bfloat16*)smraw;
    __nv_bfloat16* Alo = Ahi + 128 * PLD;
    __nv_bfloat16* Bhi = Alo + 128 * PLD;
    __nv_bfloat16* Blo = Bhi + 128 * PLD;

    int tid = threadIdx.x, wid = tid >> 5;
    int n0 = blockIdx.x * 128, m0 = blockIdx.y * 128, which = blockIdx.z;

    const __nv_bfloat16* Xh = g_Xhi + (size_t)m0 * DIM;
    const __nv_bfloat16* Xl = g_Xlo + (size_t)m0 * DIM;
    const __nv_bfloat16* Wh = g_Whi[which] + (size_t)n0 * DIM;
    const __nv_bfloat16* Wl = g_Wlo[which] + (size_t)n0 * DIM;

    wmma::fragment<wmma::accumulator, 16, 16, 16, float> c[4][2];
    #pragma unroll
    for (int i = 0; i < 4; i++)
        #pragma unroll
        for (int j = 0; j < 2; j++) wmma::fill_fragment(c[i][j], 0.f);

    int wm = (wid >> 2) * 64, wn = (wid & 3) * 32;

    for (int k0 = 0; k0 < DIM; k0 += 32) {
        __syncthreads();
        #pragma unroll
        for (int i = 0; i < 2; i++) {
            int idx = tid + i * 256;         // 0..511
            int row = idx >> 2, c8 = (idx & 3) * 8;
            *(uint4*)&Ahi[row * PLD + c8] = *(const uint4*)&Xh[row * DIM + k0 + c8];
            *(uint4*)&Alo[row * PLD + c8] = *(const uint4*)&Xl[row * DIM + k0 + c8];
            *(uint4*)&Bhi[row * PLD + c8] = *(const uint4*)&Wh[row * DIM + k0 + c8];
            *(uint4*)&Blo[row * PLD + c8] = *(const uint4*)&Wl[row * DIM + k0 + c8];
        }
        __syncthreads();

        #pragma unroll
        for (int ks = 0; ks < 2; ks++) {
            wmma::fragment<wmma::matrix_a, 16, 16, 16, __nv_bfloat16, wmma::row_major> ah[4], al[4];
            wmma::fragment<wmma::matrix_b, 16, 16, 16, __nv_bfloat16, wmma::col_major> bh[2], bl[2];
            #pragma unroll
            for (int i = 0; i < 4; i++) {
                wmma::load_matrix_sync(ah[i], &Ahi[(wm + 16 * i) * PLD + ks * 16], PLD);
                wmma::load_matrix_sync(al[i], &Alo[(wm + 16 * i) * PLD + ks * 16], PLD);
            }
            #pragma unroll
            for (int j = 0; j < 2; j++) {
                wmma::load_matrix_sync(bh[j], &Bhi[(wn + 16 * j) * PLD + ks * 16], PLD);
                wmma::load_matrix_sync(bl[j], &Blo[(wn + 16 * j) * PLD + ks * 16], PLD);
            }
            #pragma unroll
            for (int i = 0; i < 4; i++)
                #pragma unroll
                for (int j = 0; j < 2; j++) {
                    wmma::mma_sync(c[i][j], ah[i], bh[j], c[i][j]);
                    wmma::mma_sync(c[i][j], ah[i], bl[j], c[i][j]);
                    wmma::mma_sync(c[i][j], al[i], bh[j], c[i][j]);
                }
        }
    }

    // Canonical direct-to-global accumulator store (row-major, ldm = DIM)
    float* Y = g_Y[which];
    #pragma unroll
    for (int i = 0; i < 4; i++)
        #pragma unroll
        for (int j = 0; j < 2; j++)
            wmma::store_matrix_sync(&Y[(size_t)(m0 + wm + 16 * i) * DIM + n0 + wn + 16 * j],
                                    c[i][j], DIM, wmma::mem_row_major);
}

// ---------------------------------------------------------------------------
// finish: bias + RoPE + transpose  g_Y[which] -> g_Q/g_K/g_V [B,H,S,HD] fp32.
// One thread = (row m, head h, quarter q): features q*4..q*4+3 and +32.
// ---------------------------------------------------------------------------
__global__ __launch_bounds__(256) void finish_kernel(
    const float* __restrict__ bq, const float* __restrict__ bk,
    const float* __restrict__ bv)
{
    int which = blockIdx.z;
    int gidx = blockIdx.x * 256 + threadIdx.x;   // 0 .. MTOT*16*8-1
    int q = gidx & 7;
    int h = (gidx >> 3) & 15;
    int m = gidx >> 7;
    int b = m / SEQ, s = m % SEQ;
    int c0 = q * 4;

    const float* Yrow = g_Y[which] + (size_t)m * DIM + h * HD;
    const float* bias = (which == 0) ? bq : (which == 1) ? bk : bv;

    float4 x1 = *(const float4*)(Yrow + c0);
    float4 x2 = *(const float4*)(Yrow + c0 + DH);
    x1.x += bias[h * HD + c0];     x1.y += bias[h * HD + c0 + 1];
    x1.z += bias[h * HD + c0 + 2]; x1.w += bias[h * HD + c0 + 3];
    x2.x += bias[h * HD + c0 + DH];     x2.y += bias[h * HD + c0 + DH + 1];
    x2.z += bias[h * HD + c0 + DH + 2]; x2.w += bias[h * HD + c0 + DH + 3];

    float4 o1 = x1, o2 = x2;
    if (which != 2) {
        float sn0 = g_sin[s * DH + c0],     cs0 = g_cos[s * DH + c0];
        float sn1 = g_sin[s * DH + c0 + 1], cs1 = g_cos[s * DH + c0 + 1];
        float sn2 = g_sin[s * DH + c0 + 2], cs2 = g_cos[s * DH + c0 + 2];
        float sn3 = g_sin[s * DH + c0 + 3], cs3 = g_cos[s * DH + c0 + 3];
        o1.x = x1.x * cs0 - x2.x * sn0;  o2.x = x1.x * sn0 + x2.x * cs0;
        o1.y = x1.y * cs1 - x2.y * sn1;  o2.y = x1.y * sn1 + x2.y * cs1;
        o1.z = x1.z * cs2 - x2.z * sn2;  o2.z = x1.z * sn2 + x2.z * cs2;
        o1.w = x1.w * cs3 - x2.w * sn3;  o2.w = x1.w * sn3 + x2.w * cs3;
    }
    float* outp = (which == 0) ? g_Q : (which == 1) ? g_K : g_V;
    float* dst = outp + ((size_t)(b * NH + h) * SEQ + s) * HD;
    *(float4*)(dst + c0) = o1;
    *(float4*)(dst + c0 + DH) = o2;
}

// ---------------------------------------------------------------------------
// Flash attention (SIMT) — VERBATIM from the round-1 passing kernel.
// ---------------------------------------------------------------------------
__global__ __launch_bounds__(256) void attn_kernel(float* __restrict__ out) {
    extern __shared__ float smf[];
    float* q_sh = smf;
    float* k_sh = q_sh + 64 * 65;
    float* v_sh = k_sh + 64 * 65;
    float* s_sh = v_sh + 64 * 65;
    float* m_sh = s_sh + 64 * 65;
    float* l_sh = m_sh + 64;
    float* al_sh = l_sh + 64;

    int tid = threadIdx.x;
    int q0 = blockIdx.x * 64;
    int bh = blockIdx.y;
    int b = bh / NH, h = bh % NH;

    const float* Qb = g_Q + (size_t)bh * SEQ * HD;
    const float* Kb = g_K + (size_t)bh * SEQ * HD;
    const float* Vb = g_V + (size_t)bh * SEQ * HD;

    #pragma unroll
    for (int i = 0; i < 16; i++) {
        int idx = tid + i * 256;
        int r = idx >> 6, c = idx & 63;
        q_sh[r * 65 + c] = Qb[(q0 + r) * HD + c];
    }
    if (tid < 64) { m_sh[tid] = -INFINITY; l_sh[tid] = 0.f; }

    int ti = tid >> 4, tj = tid & 15;
    float acc[4][4] = {};

    for (int kt = 0; kt < SEQ / 64; kt++) {
        __syncthreads();
        #pragma unroll
        for (int i = 0; i < 16; i++) {
            int idx = tid + i * 256;
            int r = idx >> 6, c = idx & 63;
            k_sh[r * 65 + c] = Kb[(kt * 64 + r) * HD + c];
            v_sh[r * 65 + c] = Vb[(kt * 64 + r) * HD + c];
        }
        __syncthreads();

        float sc[4][4] = {};
        #pragma unroll 8
        for (int d = 0; d < 64; d++) {
            float a[4], bb[4];
            #pragma unroll
            for (int i = 0; i < 4; i++) a[i] = q_sh[(ti * 4 + i) * 65 + d];
            #pragma unroll
            for (int j = 0; j < 4; j++) bb[j] = k_sh[(tj * 4 + j) * 65 + d];
            #pragma unroll
            for (int i = 0; i < 4; i++)
                #pragma unroll
                for (int j = 0; j < 4; j++)
                    sc[i][j] += a[i] * bb[j];
        }
        #pragma unroll
        for (int i = 0; i < 4; i++)
            #pragma unroll
            for (int j = 0; j < 4; j++)
                s_sh[(ti * 4 + i) * 65 + tj * 4 + j] = sc[i][j] * SCALE;
        __syncthreads();

        {
            int r = tid >> 2, g = tid & 3;
            float* row = s_sh + r * 65 + g * 16;
            float mx = -INFINITY;
            #pragma unroll
            for (int j = 0; j < 16; j++) mx = fmaxf(mx, row[j]);
            mx = fmaxf(mx, __shfl_xor_sync(0xffffffffu, mx, 1));
            mx = fmaxf(mx, __shfl_xor_sync(0xffffffffu, mx, 2));
            float m_old = m_sh[r];
            float m_new = fmaxf(m_old, mx);
            float alpha = expf(m_old - m_new);
            float sum = 0.f;
            #pragma unroll
            for (int j = 0; j < 16; j++) {
                float p = expf(row[j] - m_new);
                row[j] = p;
                sum += p;
            }
            sum += __shfl_xor_sync(0xffffffffu, sum, 1);
            sum += __shfl_xor_sync(0xffffffffu, sum, 2);
            __syncwarp();
            if (g == 0) {
                m_sh[r] = m_new;
                l_sh[r] = l_sh[r] * alpha + sum;
                al_sh[r] = alpha;
            }
        }
        __syncthreads();

        float alp[4];
        #pragma unroll
        for (int i = 0; i < 4; i++) alp[i] = al_sh[ti * 4 + i];
        #pragma unroll
        for (int i = 0; i < 4; i++)
            #pragma unroll
            for (int j = 0; j < 4; j++)
                acc[i][j] *= alp[i];
        #pragma unroll 8
        for (int jj = 0; jj < 64; jj++) {
            float p[4], vv[4];
            #pragma unroll
            for (int i = 0; i < 4; i++) p[i] = s_sh[(ti * 4 + i) * 65 + jj];
            #pragma unroll
            for (int j = 0; j < 4; j++) vv[j] = v_sh[jj * 65 + tj * 4 + j];
            #pragma unroll
            for (int i = 0; i < 4; i++)
                #pragma unroll
                for (int j = 0; j < 4; j++)
                    acc[i][j] += p[i] * vv[j];
        }
    }
    __syncthreads();

    float linv[4];
    #pragma unroll
    for (int i = 0; i < 4; i++) linv[i] = 1.f / l_sh[ti * 4 + i];
    #pragma unroll
    for (int i = 0; i < 4; i++) {
        int s = q0 + ti * 4 + i;
        #pragma unroll
        for (int j = 0; j < 4; j++)
            out[((size_t)b * SEQ + s) * DIM + h * HD + tj * 4 + j] = acc[i][j] * linv[i];
    }
}

// ---------------------------------------------------------------------------
extern "C" void kernel_launch(void* const* d_in, const int* in_sizes, int n_in,
                              void* d_out, int out_size) {
    const float* X  = (const float*)d_in[0];
    const float* Wq = (const float*)d_in[1];
    const float* bq = (const float*)d_in[2];
    const float* Wk = (const float*)d_in[3];
    const float* bk = (const float*)d_in[4];
    const float* Wv = (const float*)d_in[5];
    const float* bv = (const float*)d_in[6];
    float* out = (float*)d_out;

    rope_table_kernel<<<(SEQ * DH + 255) / 256, 256>>>();

    split_kernel<<<(MTOT * DIM / 2 + 255) / 256, 256>>>(X, 0, MTOT * DIM / 2);
    split_kernel<<<(DIM * DIM / 2 + 255) / 256, 256>>>(Wq, 1, DIM * DIM / 2);
    split_kernel<<<(DIM * DIM / 2 + 255) / 256, 256>>>(Wk, 2, DIM * DIM / 2);
    split_kernel<<<(DIM * DIM / 2 + 255) / 256, 256>>>(Wv, 3, DIM * DIM / 2);

    cudaFuncSetAttribute(gemm_wmma, cudaFuncAttributeMaxDynamicSharedMemorySize, PROJ_SMEM);
    dim3 ggrid(DIM / 128, MTOT / 128, 3);
    gemm_wmma<<<ggrid, 256, PROJ_SMEM>>>();

    dim3 fgrid(MTOT * 16 * 8 / 256, 1, 3);
    finish_kernel<<<fgrid, 256>>>(bq, bk, bv);

    int smem = (4 * 64 * 65 + 3 * 64) * (int)sizeof(float);
    cudaFuncSetAttribute(attn_kernel, cudaFuncAttributeMaxDynamicSharedMemorySize, smem);
    dim3 agrid(SEQ / 64, BATCH * NH);
    attn_kernel<<<agrid, 256, smem>>>(out);
}

// round 6
// speedup vs baseline: 2.1269x; 1.4229x over previous
#include <cuda_runtime.h>
#include <cuda_bf16.h>
#include <mma.h>
#include <math.h>
#include <stdint.h>

using namespace nvcuda;

#define BATCH 2
#define SEQ 2048
#define DIM 1024
#define NH 16
#define HD 64
#define DH 32
#define MTOT (BATCH*SEQ)   // 4096
#define SCALE 0.125f

// ---------------- device scratch (no allocation allowed) -------------------
__device__ float g_Y[3][MTOT*DIM];
__device__ float g_sin[SEQ*DH], g_cos[SEQ*DH];
__device__ __nv_bfloat16 g_Xhi[MTOT*DIM], g_Xlo[MTOT*DIM];
__device__ __nv_bfloat16 g_Whi[3][DIM*DIM], g_Wlo[3][DIM*DIM];
__device__ __nv_bfloat16 g_Qhi[MTOT*DIM], g_Qlo[MTOT*DIM];
__device__ __nv_bfloat16 g_Khi[MTOT*DIM], g_Klo[MTOT*DIM];
__device__ __nv_bfloat16 g_Vhi[MTOT*DIM], g_Vlo[MTOT*DIM];

// ---------------------------------------------------------------------------
// RoPE tables in double precision (safe at large angles)
// ---------------------------------------------------------------------------
__global__ void rope_table_kernel() {
    int idx = blockIdx.x * blockDim.x + threadIdx.x;
    if (idx >= SEQ * DH) return;
    int s = idx / DH, i = idx % DH;
    double ang = (double)s * pow(10000.0, -((double)i) / (double)DH);
    g_sin[idx] = (float)sin(ang);
    g_cos[idx] = (float)cos(ang);
}

// ---------------------------------------------------------------------------
// Split fp32 -> bf16 hi + bf16 lo.  which: 0=X, 1..3=W[0..2]
// ---------------------------------------------------------------------------
__global__ void split_kernel(const float* __restrict__ src, int which, int n2) {
    __nv_bfloat16* hi = (which == 0) ? g_Xhi : g_Whi[which - 1];
    __nv_bfloat16* lo = (which == 0) ? g_Xlo : g_Wlo[which - 1];
    int i = blockIdx.x * blockDim.x + threadIdx.x;
    if (i >= n2) return;
    float2 x = ((const float2*)src)[i];
    float h0 = __bfloat162float(__float2bfloat16(x.x));
    float h1 = __bfloat162float(__float2bfloat16(x.y));
    __nv_bfloat162 hh, ll;
    hh.x = __float2bfloat16(h0);
    hh.y = __float2bfloat16(h1);
    ll.x = __float2bfloat16(x.x - h0);
    ll.y = __float2bfloat16(x.y - h1);
    ((__nv_bfloat162*)hi)[i] = hh;
    ((__nv_bfloat162*)lo)[i] = ll;
}

// ---------------------------------------------------------------------------
// Pure WMMA GEMM: g_Y[which] = X @ W[which]^T  (bf16 hi/lo split, 3 MMAs).
// Tile 128x128, 8 warps (2m x 4n), k-chunk 32. VERIFIED in round 5.
// ---------------------------------------------------------------------------
#define PLD 40      // bf16 smem ld
#define PROJ_SMEM (4 * 128 * PLD * 2)   // 40960 bytes

__global__ __launch_bounds__(256) void gemm_wmma() {
    extern __shared__ __align__(128) char smraw[];
    __nv_bfloat16* Ahi = (__nv_bfloat16*)smraw;
    __nv_bfloat16* Alo = Ahi + 128 * PLD;
    __nv_bfloat16* Bhi = Alo + 128 * PLD;
    __nv_bfloat16* Blo = Bhi + 128 * PLD;

    int tid = threadIdx.x, wid = tid >> 5;
    int n0 = blockIdx.x * 128, m0 = blockIdx.y * 128, which = blockIdx.z;

    const __nv_bfloat16* Xh = g_Xhi + (size_t)m0 * DIM;
    const __nv_bfloat16* Xl = g_Xlo + (size_t)m0 * DIM;
    const __nv_bfloat16* Wh = g_Whi[which] + (size_t)n0 * DIM;
    const __nv_bfloat16* Wl = g_Wlo[which] + (size_t)n0 * DIM;

    wmma::fragment<wmma::accumulator, 16, 16, 16, float> c[4][2];
    #pragma unroll
    for (int i = 0; i < 4; i++)
        #pragma unroll
        for (int j = 0; j < 2; j++) wmma::fill_fragment(c[i][j], 0.f);

    int wm = (wid >> 2) * 64, wn = (wid & 3) * 32;

    for (int k0 = 0; k0 < DIM; k0 += 32) {
        __syncthreads();
        #pragma unroll
        for (int i = 0; i < 2; i++) {
            int idx = tid + i * 256;         // 0..511
            int row = idx >> 2, c8 = (idx & 3) * 8;
            *(uint4*)&Ahi[row * PLD + c8] = *(const uint4*)&Xh[row * DIM + k0 + c8];
            *(uint4*)&Alo[row * PLD + c8] = *(const uint4*)&Xl[row * DIM + k0 + c8];
            *(uint4*)&Bhi[row * PLD + c8] = *(const uint4*)&Wh[row * DIM + k0 + c8];
            *(uint4*)&Blo[row * PLD + c8] = *(const uint4*)&Wl[row * DIM + k0 + c8];
        }
        __syncthreads();

        #pragma unroll
        for (int ks = 0; ks < 2; ks++) {
            wmma::fragment<wmma::matrix_a, 16, 16, 16, __nv_bfloat16, wmma::row_major> ah[4], al[4];
            wmma::fragment<wmma::matrix_b, 16, 16, 16, __nv_bfloat16, wmma::col_major> bh[2], bl[2];
            #pragma unroll
            for (int i = 0; i < 4; i++) {
                wmma::load_matrix_sync(ah[i], &Ahi[(wm + 16 * i) * PLD + ks * 16], PLD);
                wmma::load_matrix_sync(al[i], &Alo[(wm + 16 * i) * PLD + ks * 16], PLD);
            }
            #pragma unroll
            for (int j = 0; j < 2; j++) {
                wmma::load_matrix_sync(bh[j], &Bhi[(wn + 16 * j) * PLD + ks * 16], PLD);
                wmma::load_matrix_sync(bl[j], &Blo[(wn + 16 * j) * PLD + ks * 16], PLD);
            }
            #pragma unroll
            for (int i = 0; i < 4; i++)
                #pragma unroll
                for (int j = 0; j < 2; j++) {
                    wmma::mma_sync(c[i][j], ah[i], bh[j], c[i][j]);
                    wmma::mma_sync(c[i][j], ah[i], bl[j], c[i][j]);
                    wmma::mma_sync(c[i][j], al[i], bh[j], c[i][j]);
                }
        }
    }

    float* Y = g_Y[which];
    #pragma unroll
    for (int i = 0; i < 4; i++)
        #pragma unroll
        for (int j = 0; j < 2; j++)
            wmma::store_matrix_sync(&Y[(size_t)(m0 + wm + 16 * i) * DIM + n0 + wn + 16 * j],
                                    c[i][j], DIM, wmma::mem_row_major);
}

// ---------------------------------------------------------------------------
// finish: bias + RoPE + transpose  g_Y[which] -> bf16 hi/lo [B,H,S,HD].
// One thread = (row m, head h, quarter q): features q*4..q*4+3 and +32.
// ---------------------------------------------------------------------------
__global__ __launch_bounds__(256) void finish_kernel(
    const float* __restrict__ bq, const float* __restrict__ bk,
    const float* __restrict__ bv)
{
    int which = blockIdx.z;
    int gidx = blockIdx.x * 256 + threadIdx.x;   // 0 .. MTOT*16*8-1
    int q = gidx & 7;
    int h = (gidx >> 3) & 15;
    int m = gidx >> 7;
    int b = m / SEQ, s = m % SEQ;
    int c0 = q * 4;

    const float* Yrow = g_Y[which] + (size_t)m * DIM + h * HD;
    const float* bias = (which == 0) ? bq : (which == 1) ? bk : bv;

    float4 x1 = *(const float4*)(Yrow + c0);
    float4 x2 = *(const float4*)(Yrow + c0 + DH);
    x1.x += bias[h * HD + c0];     x1.y += bias[h * HD + c0 + 1];
    x1.z += bias[h * HD + c0 + 2]; x1.w += bias[h * HD + c0 + 3];
    x2.x += bias[h * HD + c0 + DH];     x2.y += bias[h * HD + c0 + DH + 1];
    x2.z += bias[h * HD + c0 + DH + 2]; x2.w += bias[h * HD + c0 + DH + 3];

    float o1[4] = {x1.x, x1.y, x1.z, x1.w};
    float o2[4] = {x2.x, x2.y, x2.z, x2.w};
    if (which != 2) {
        #pragma unroll
        for (int t = 0; t < 4; t++) {
            float sn = g_sin[s * DH + c0 + t], cs = g_cos[s * DH + c0 + t];
            float a = o1[t], bb = o2[t];
            o1[t] = a * cs - bb * sn;
            o2[t] = a * sn + bb * cs;
        }
    }
    __nv_bfloat16* ph = (which == 0) ? g_Qhi : (which == 1) ? g_Khi : g_Vhi;
    __nv_bfloat16* pl = (which == 0) ? g_Qlo : (which == 1) ? g_Klo : g_Vlo;
    size_t base = ((size_t)(b * NH + h) * SEQ + s) * HD;
    #pragma unroll
    for (int half = 0; half < 2; half++) {
        float* o = half ? o2 : o1;
        size_t off = base + c0 + half * DH;
        __nv_bfloat162 hh0, hh1, ll0, ll1;
        hh0.x = __float2bfloat16(o[0]); hh0.y = __float2bfloat16(o[1]);
        hh1.x = __float2bfloat16(o[2]); hh1.y = __float2bfloat16(o[3]);
        ll0.x = __float2bfloat16(o[0] - __bfloat162float(hh0.x));
        ll0.y = __float2bfloat16(o[1] - __bfloat162float(hh0.y));
        ll1.x = __float2bfloat16(o[2] - __bfloat162float(hh1.x));
        ll1.y = __float2bfloat16(o[3] - __bfloat162float(hh1.y));
        *(__nv_bfloat162*)(ph + off)     = hh0;
        *(__nv_bfloat162*)(ph + off + 2) = hh1;
        *(__nv_bfloat162*)(pl + off)     = ll0;
        *(__nv_bfloat162*)(pl + off + 2) = ll1;
    }
}

// ---------------------------------------------------------------------------
// WMMA flash attention, 64q x 64k tiles, 4 warps (2m x 2n).
// Unnormalized exp (scores bounded) -> running row-sum, divide at the end.
// Separate smem buffers, NO overlays/retyping.
// ---------------------------------------------------------------------------
#define ALD 72      // bf16 smem ld
#define SLD 68      // fp32 smem ld
#define OFF_QHI 0
#define OFF_QLO (OFF_QHI + 64*ALD*2)
#define OFF_KHI (OFF_QLO + 64*ALD*2)
#define OFF_KLO (OFF_KHI + 64*ALD*2)
#define OFF_VHI (OFF_KLO + 64*ALD*2)
#define OFF_VLO (OFF_VHI + 64*ALD*2)
#define OFF_PHI (OFF_VLO + 64*ALD*2)
#define OFF_PLO (OFF_PHI + 64*ALD*2)
#define OFF_S   (OFF_PLO + 64*ALD*2)
#define OFF_L   (OFF_S + 64*SLD*4)
#define ATTN_SMEM (OFF_L + 64*4)

__global__ __launch_bounds__(128) void attn_wmma(float* __restrict__ out) {
    extern __shared__ __align__(128) char smraw[];
    __nv_bfloat16* Qhi_s = (__nv_bfloat16*)(smraw + OFF_QHI);
    __nv_bfloat16* Qlo_s = (__nv_bfloat16*)(smraw + OFF_QLO);
    __nv_bfloat16* Khi_s = (__nv_bfloat16*)(smraw + OFF_KHI);
    __nv_bfloat16* Klo_s = (__nv_bfloat16*)(smraw + OFF_KLO);
    __nv_bfloat16* Vhi_s = (__nv_bfloat16*)(smraw + OFF_VHI);
    __nv_bfloat16* Vlo_s = (__nv_bfloat16*)(smraw + OFF_VLO);
    __nv_bfloat16* Phi_s = (__nv_bfloat16*)(smraw + OFF_PHI);
    __nv_bfloat16* Plo_s = (__nv_bfloat16*)(smraw + OFF_PLO);
    float* Ssh = (float*)(smraw + OFF_S);
    float* Lsh = (float*)(smraw + OFF_L);

    int tid = threadIdx.x, wid = tid >> 5;
    int q0 = blockIdx.x * 64, bh = blockIdx.y;
    int b = bh >> 4, h = bh & 15;

    const __nv_bfloat16* Qh = g_Qhi + ((size_t)bh * SEQ + q0) * HD;
    const __nv_bfloat16* Ql = g_Qlo + ((size_t)bh * SEQ + q0) * HD;
    const __nv_bfloat16* Kh = g_Khi + (size_t)bh * SEQ * HD;
    const __nv_bfloat16* Kl = g_Klo + (size_t)bh * SEQ * HD;
    const __nv_bfloat16* Vh = g_Vhi + (size_t)bh * SEQ * HD;
    const __nv_bfloat16* Vl = g_Vlo + (size_t)bh * SEQ * HD;

    #pragma unroll
    for (int i = 0; i < 4; i++) {
        int idx = tid + i * 128;         // 0..511
        int row = idx >> 3, c8 = (idx & 7) * 8;
        *(uint4*)&Qhi_s[row * ALD + c8] = *(const uint4*)&Qh[row * HD + c8];
        *(uint4*)&Qlo_s[row * ALD + c8] = *(const uint4*)&Ql[row * HD + c8];
    }
    if (tid < 64) Lsh[tid] = 0.f;

    int wm = (wid >> 1) * 32, wn = (wid & 1) * 32;
    wmma::fragment<wmma::accumulator, 16, 16, 16, float> ctx[2][2];
    #pragma unroll
    for (int i = 0; i < 2; i++)
        #pragma unroll
        for (int j = 0; j < 2; j++) wmma::fill_fragment(ctx[i][j], 0.f);

    for (int kt = 0; kt < SEQ / 64; kt++) {
        __syncthreads();
        #pragma unroll
        for (int i = 0; i < 4; i++) {
            int idx = tid + i * 128;
            int row = idx >> 3, c8 = (idx & 7) * 8;
            size_t g = (size_t)(kt * 64 + row) * HD + c8;
            *(uint4*)&Khi_s[row * ALD + c8] = *(const uint4*)&Kh[g];
            *(uint4*)&Klo_s[row * ALD + c8] = *(const uint4*)&Kl[g];
            *(uint4*)&Vhi_s[row * ALD + c8] = *(const uint4*)&Vh[g];
            *(uint4*)&Vlo_s[row * ALD + c8] = *(const uint4*)&Vl[g];
        }
        __syncthreads();

        // S = Q . K^T  (hi*hi + hi*lo + lo*hi) — same algebra as verified gemm
        wmma::fragment<wmma::accumulator, 16, 16, 16, float> sc[2][2];
        #pragma unroll
        for (int i = 0; i < 2; i++)
            #pragma unroll
            for (int j = 0; j < 2; j++) wmma::fill_fragment(sc[i][j], 0.f);
        #pragma unroll
        for (int ks = 0; ks < 4; ks++) {
            wmma::fragment<wmma::matrix_a, 16, 16, 16, __nv_bfloat16, wmma::row_major> ah[2], al[2];
            wmma::fragment<wmma::matrix_b, 16, 16, 16, __nv_bfloat16, wmma::col_major> bhf[2], blf[2];
            #pragma unroll
            for (int i = 0; i < 2; i++) {
                wmma::load_matrix_sync(ah[i], &Qhi_s[(wm + 16 * i) * ALD + 16 * ks], ALD);
                wmma::load_matrix_sync(al[i], &Qlo_s[(wm + 16 * i) * ALD + 16 * ks], ALD);
            }
            #pragma unroll
            for (int j = 0; j < 2; j++) {
                wmma::load_matrix_sync(bhf[j], &Khi_s[(wn + 16 * j) * ALD + 16 * ks], ALD);
                wmma::load_matrix_sync(blf[j], &Klo_s[(wn + 16 * j) * ALD + 16 * ks], ALD);
            }
            #pragma unroll
            for (int i = 0; i < 2; i++)
                #pragma unroll
                for (int j = 0; j < 2; j++) {
                    wmma::mma_sync(sc[i][j], ah[i], bhf[j], sc[i][j]);
                    wmma::mma_sync(sc[i][j], ah[i], blf[j], sc[i][j]);
                    wmma::mma_sync(sc[i][j], al[i], bhf[j], sc[i][j]);
                }
        }
        #pragma unroll
        for (int i = 0; i < 2; i++)
            #pragma unroll
            for (int j = 0; j < 2; j++)
                wmma::store_matrix_sync(&Ssh[(wm + 16 * i) * SLD + wn + 16 * j],
                                        sc[i][j], SLD, wmma::mem_row_major);
        __syncthreads();

        // exp (unnormalized), row sums, split P to bf16 hi/lo
        {
            int r = tid >> 1, c0 = (tid & 1) * 32;
            float sum = 0.f;
            #pragma unroll
            for (int cc = 0; cc < 32; cc++) {
                float p = expf(Ssh[r * SLD + c0 + cc] * SCALE);
                sum += p;
                __nv_bfloat16 hv = __float2bfloat16(p);
                Phi_s[r * ALD + c0 + cc] = hv;
                Plo_s[r * ALD + c0 + cc] = __float2bfloat16(p - __bfloat162float(hv));
            }
            sum += __shfl_xor_sync(0xffffffffu, sum, 1);
            if ((tid & 1) == 0) Lsh[r] += sum;
        }
        __syncthreads();

        // ctx += P . V  (hi*hi + hi*lo + lo*hi)
        #pragma unroll
        for (int ks = 0; ks < 4; ks++) {
            wmma::fragment<wmma::matrix_a, 16, 16, 16, __nv_bfloat16, wmma::row_major> ah[2], al[2];
            wmma::fragment<wmma::matrix_b, 16, 16, 16, __nv_bfloat16, wmma::row_major> bhf[2], blf[2];
            #pragma unroll
            for (int i = 0; i < 2; i++) {
                wmma::load_matrix_sync(ah[i], &Phi_s[(wm + 16 * i) * ALD + 16 * ks], ALD);
                wmma::load_matrix_sync(al[i], &Plo_s[(wm + 16 * i) * ALD + 16 * ks], ALD);
            }
            #pragma unroll
            for (int j = 0; j < 2; j++) {
                wmma::load_matrix_sync(bhf[j], &Vhi_s[16 * ks * ALD + wn + 16 * j], ALD);
                wmma::load_matrix_sync(blf[j], &Vlo_s[16 * ks * ALD + wn + 16 * j], ALD);
            }
            #pragma unroll
            for (int i = 0; i < 2; i++)
                #pragma unroll
                for (int j = 0; j < 2; j++) {
                    wmma::mma_sync(ctx[i][j], ah[i], bhf[j], ctx[i][j]);
                    wmma::mma_sync(ctx[i][j], ah[i], blf[j], ctx[i][j]);
                    wmma::mma_sync(ctx[i][j], al[i], bhf[j], ctx[i][j]);
                }
        }
    }
    __syncthreads();
    #pragma unroll
    for (int i = 0; i < 2; i++)
        #pragma unroll
        for (int j = 0; j < 2; j++)
            wmma::store_matrix_sync(&Ssh[(wm + 16 * i) * SLD + wn + 16 * j],
                                    ctx[i][j], SLD, wmma::mem_row_major);
    __syncthreads();

    {
        int r = tid >> 1, c0 = (tid & 1) * 32;
        float linv = 1.f / Lsh[r];
        int s = q0 + r;
        float* dst = out + ((size_t)b * SEQ + s) * DIM + h * HD + c0;
        #pragma unroll
        for (int cc = 0; cc < 32; cc += 4) {
            float4 v;
            v.x = Ssh[r * SLD + c0 + cc]     * linv;
            v.y = Ssh[r * SLD + c0 + cc + 1] * linv;
            v.z = Ssh[r * SLD + c0 + cc + 2] * linv;
            v.w = Ssh[r * SLD + c0 + cc + 3] * linv;
            *(float4*)(dst + cc) = v;
        }
    }
}

// ---------------------------------------------------------------------------
extern "C" void kernel_launch(void* const* d_in, const int* in_sizes, int n_in,
                              void* d_out, int out_size) {
    const float* X  = (const float*)d_in[0];
    const float* Wq = (const float*)d_in[1];
    const float* bq = (const float*)d_in[2];
    const float* Wk = (const float*)d_in[3];
    const float* bk = (const float*)d_in[4];
    const float* Wv = (const float*)d_in[5];
    const float* bv = (const float*)d_in[6];
    float* out = (float*)d_out;

    rope_table_kernel<<<(SEQ * DH + 255) / 256, 256>>>();

    split_kernel<<<(MTOT * DIM / 2 + 255) / 256, 256>>>(X, 0, MTOT * DIM / 2);
    split_kernel<<<(DIM * DIM / 2 + 255) / 256, 256>>>(Wq, 1, DIM * DIM / 2);
    split_kernel<<<(DIM * DIM / 2 + 255) / 256, 256>>>(Wk, 2, DIM * DIM / 2);
    split_kernel<<<(DIM * DIM / 2 + 255) / 256, 256>>>(Wv, 3, DIM * DIM / 2);

    cudaFuncSetAttribute(gemm_wmma, cudaFuncAttributeMaxDynamicSharedMemorySize, PROJ_SMEM);
    dim3 ggrid(DIM / 128, MTOT / 128, 3);
    gemm_wmma<<<ggrid, 256, PROJ_SMEM>>>();

    dim3 fgrid(MTOT * 16 * 8 / 256, 1, 3);
    finish_kernel<<<fgrid, 256>>>(bq, bk, bv);

    cudaFuncSetAttribute(attn_wmma, cudaFuncAttributeMaxDynamicSharedMemorySize, ATTN_SMEM);
    dim3 agrid(SEQ / 64, BATCH * NH);
    attn_wmma<<<agrid, 128, ATTN_SMEM>>>(out);
}

// round 8
// speedup vs baseline: 2.1706x; 1.0205x over previous
#include <cuda_runtime.h>
#include <cuda_bf16.h>
#include <mma.h>
#include <math.h>
#include <stdint.h>

using namespace nvcuda;

#define BATCH 2
#define SEQ 2048
#define DIM 1024
#define NH 16
#define HD 64
#define DH 32
#define MTOT (BATCH*SEQ)   // 4096
#define SCALE 0.125f

// ---------------- device scratch (no allocation allowed) -------------------
__device__ float g_Y[3][MTOT*DIM];
__device__ float g_sin[SEQ*DH], g_cos[SEQ*DH];
__device__ __nv_bfloat16 g_Xhi[MTOT*DIM], g_Xlo[MTOT*DIM];
__device__ __nv_bfloat16 g_Whi[3][DIM*DIM], g_Wlo[3][DIM*DIM];
__device__ __nv_bfloat16 g_Qhi[MTOT*DIM], g_Qlo[MTOT*DIM];
__device__ __nv_bfloat16 g_Khi[MTOT*DIM], g_Klo[MTOT*DIM];
__device__ __nv_bfloat16 g_Vhi[MTOT*DIM], g_Vlo[MTOT*DIM];

// ---------------------------------------------------------------------------
// RoPE tables in double precision (safe at large angles)
// ---------------------------------------------------------------------------
__global__ void rope_table_kernel() {
    int idx = blockIdx.x * blockDim.x + threadIdx.x;
    if (idx >= SEQ * DH) return;
    int s = idx / DH, i = idx % DH;
    double ang = (double)s * pow(10000.0, -((double)i) / (double)DH);
    g_sin[idx] = (float)sin(ang);
    g_cos[idx] = (float)cos(ang);
}

// ---------------------------------------------------------------------------
// Split fp32 -> bf16 hi + bf16 lo.  which: 0=X, 1..3=W[0..2]
// ---------------------------------------------------------------------------
__global__ void split_kernel(const float* __restrict__ src, int which, int n2) {
    __nv_bfloat16* hi = (which == 0) ? g_Xhi : g_Whi[which - 1];
    __nv_bfloat16* lo = (which == 0) ? g_Xlo : g_Wlo[which - 1];
    int i = blockIdx.x * blockDim.x + threadIdx.x;
    if (i >= n2) return;
    float2 x = ((const float2*)src)[i];
    float h0 = __bfloat162float(__float2bfloat16(x.x));
    float h1 = __bfloat162float(__float2bfloat16(x.y));
    __nv_bfloat162 hh, ll;
    hh.x = __float2bfloat16(h0);
    hh.y = __float2bfloat16(h1);
    ll.x = __float2bfloat16(x.x - h0);
    ll.y = __float2bfloat16(x.y - h1);
    ((__nv_bfloat162*)hi)[i] = hh;
    ((__nv_bfloat162*)lo)[i] = ll;
}

// ---------------------------------------------------------------------------
// WMMA GEMM: g_Y[which] = X @ W[which]^T  (bf16 hi/lo split, 3 MMAs).
// Tile 128x128, 8 warps (2m x 4n), k-chunk 64.
// ---------------------------------------------------------------------------
#define PLD 72      // bf16 smem ld for 64-wide k-chunk
#define PROJ_SMEM (4 * 128 * PLD * 2)   // 73728 bytes

__global__ __launch_bounds__(256) void gemm_wmma() {
    extern __shared__ __align__(128) char smraw[];
    __nv_bfloat16* Ahi = (__nv_bfloat16*)smraw;
    __nv_bfloat16* Alo = Ahi + 128 * PLD;
    __nv_bfloat16* Bhi = Alo + 128 * PLD;
    __nv_bfloat16* Blo = Bhi + 128 * PLD;

    int tid = threadIdx.x, wid = tid >> 5;
    int n0 = blockIdx.x * 128, m0 = blockIdx.y * 128, which = blockIdx.z;

    const __nv_bfloat16* Xh = g_Xhi + (size_t)m0 * DIM;
    const __nv_bfloat16* Xl = g_Xlo + (size_t)m0 * DIM;
    const __nv_bfloat16* Wh = g_Whi[which] + (size_t)n0 * DIM;
    const __nv_bfloat16* Wl = g_Wlo[which] + (size_t)n0 * DIM;

    wmma::fragment<wmma::accumulator, 16, 16, 16, float> c[4][2];
    #pragma unroll
    for (int i = 0; i < 4; i++)
        #pragma unroll
        for (int j = 0; j < 2; j++) wmma::fill_fragment(c[i][j], 0.f);

    int wm = (wid >> 2) * 64, wn = (wid & 3) * 32;

    for (int k0 = 0; k0 < DIM; k0 += 64) {
        __syncthreads();
        #pragma unroll
        for (int i = 0; i < 4; i++) {
            int idx = tid + i * 256;         // 0..1023
            int row = idx >> 3, c8 = (idx & 7) * 8;
            *(uint4*)&Ahi[row * PLD + c8] = *(const uint4*)&Xh[row * DIM + k0 + c8];
            *(uint4*)&Alo[row * PLD + c8] = *(const uint4*)&Xl[row * DIM + k0 + c8];
            *(uint4*)&Bhi[row * PLD + c8] = *(const uint4*)&Wh[row * DIM + k0 + c8];
            *(uint4*)&Blo[row * PLD + c8] = *(const uint4*)&Wl[row * DIM + k0 + c8];
        }
        __syncthreads();

        #pragma unroll
        for (int ks = 0; ks < 4; ks++) {
            wmma::fragment<wmma::matrix_a, 16, 16, 16, __nv_bfloat16, wmma::row_major> ah[4], al[4];
            wmma::fragment<wmma::matrix_b, 16, 16, 16, __nv_bfloat16, wmma::col_major> bh[2], bl[2];
            #pragma unroll
            for (int i = 0; i < 4; i++) {
                wmma::load_matrix_sync(ah[i], &Ahi[(wm + 16 * i) * PLD + ks * 16], PLD);
                wmma::load_matrix_sync(al[i], &Alo[(wm + 16 * i) * PLD + ks * 16], PLD);
            }
            #pragma unroll
            for (int j = 0; j < 2; j++) {
                wmma::load_matrix_sync(bh[j], &Bhi[(wn + 16 * j) * PLD + ks * 16], PLD);
                wmma::load_matrix_sync(bl[j], &Blo[(wn + 16 * j) * PLD + ks * 16], PLD);
            }
            #pragma unroll
            for (int i = 0; i < 4; i++)
                #pragma unroll
                for (int j = 0; j < 2; j++) {
                    wmma::mma_sync(c[i][j], ah[i], bh[j], c[i][j]);
                    wmma::mma_sync(c[i][j], ah[i], bl[j], c[i][j]);
                    wmma::mma_sync(c[i][j], al[i], bh[j], c[i][j]);
                }
        }
    }

    float* Y = g_Y[which];
    #pragma unroll
    for (int i = 0; i < 4; i++)
        #pragma unroll
        for (int j = 0; j < 2; j++)
            wmma::store_matrix_sync(&Y[(size_t)(m0 + wm + 16 * i) * DIM + n0 + wn + 16 * j],
                                    c[i][j], DIM, wmma::mem_row_major);
}

// ---------------------------------------------------------------------------
// finish: bias + RoPE + transpose  g_Y[which] -> bf16 hi/lo [B,H,S,HD].
// ---------------------------------------------------------------------------
__global__ __launch_bounds__(256) void finish_kernel(
    const float* __restrict__ bq, const float* __restrict__ bk,
    const float* __restrict__ bv)
{
    int which = blockIdx.z;
    int gidx = blockIdx.x * 256 + threadIdx.x;   // 0 .. MTOT*16*8-1
    int q = gidx & 7;
    int h = (gidx >> 3) & 15;
    int m = gidx >> 7;
    int b = m / SEQ, s = m % SEQ;
    int c0 = q * 4;

    const float* Yrow = g_Y[which] + (size_t)m * DIM + h * HD;
    const float* bias = (which == 0) ? bq : (which == 1) ? bk : bv;

    float4 x1 = *(const float4*)(Yrow + c0);
    float4 x2 = *(const float4*)(Yrow + c0 + DH);
    x1.x += bias[h * HD + c0];     x1.y += bias[h * HD + c0 + 1];
    x1.z += bias[h * HD + c0 + 2]; x1.w += bias[h * HD + c0 + 3];
    x2.x += bias[h * HD + c0 + DH];     x2.y += bias[h * HD + c0 + DH + 1];
    x2.z += bias[h * HD + c0 + DH + 2]; x2.w += bias[h * HD + c0 + DH + 3];

    float o1[4] = {x1.x, x1.y, x1.z, x1.w};
    float o2[4] = {x2.x, x2.y, x2.z, x2.w};
    if (which != 2) {
        #pragma unroll
        for (int t = 0; t < 4; t++) {
            float sn = g_sin[s * DH + c0 + t], cs = g_cos[s * DH + c0 + t];
            float a = o1[t], bb = o2[t];
            o1[t] = a * cs - bb * sn;
            o2[t] = a * sn + bb * cs;
        }
    }
    __nv_bfloat16* ph = (which == 0) ? g_Qhi : (which == 1) ? g_Khi : g_Vhi;
    __nv_bfloat16* pl = (which == 0) ? g_Qlo : (which == 1) ? g_Klo : g_Vlo;
    size_t base = ((size_t)(b * NH + h) * SEQ + s) * HD;
    #pragma unroll
    for (int half = 0; half < 2; half++) {
        float* o = half ? o2 : o1;
        size_t off = base + c0 + half * DH;
        __nv_bfloat162 hh0, hh1, ll0, ll1;
        hh0.x = __float2bfloat16(o[0]); hh0.y = __float2bfloat16(o[1]);
        hh1.x = __float2bfloat16(o[2]); hh1.y = __float2bfloat16(o[3]);
        ll0.x = __float2bfloat16(o[0] - __bfloat162float(hh0.x));
        ll0.y = __float2bfloat16(o[1] - __bfloat162float(hh0.y));
        ll1.x = __float2bfloat16(o[2] - __bfloat162float(hh1.x));
        ll1.y = __float2bfloat16(o[3] - __bfloat162float(hh1.y));
        *(__nv_bfloat162*)(ph + off)     = hh0;
        *(__nv_bfloat162*)(ph + off + 2) = hh1;
        *(__nv_bfloat162*)(pl + off)     = ll0;
        *(__nv_bfloat162*)(pl + off + 2) = ll1;
    }
}

// ---------------------------------------------------------------------------
// WMMA flash attention: 128q x 64k tiles, 8 warps (4m x 2n), 256 threads.
// QK^T: hi/lo 3 MMAs.  P.V: 3 MMAs (Ph.Vh + Ph.Vl + Pl.Vh) — both lo terms
// REQUIRED: output rel-err ≈ per-element quantization error (no averaging).
// Unnormalized exp + running row-sum; divide at the end. No smem overlays.
// ---------------------------------------------------------------------------
#define TQ 128
#define ALD 72      // bf16 smem ld
#define SLD 68      // fp32 smem ld
#define OFF_QHI 0
#define OFF_QLO (OFF_QHI + TQ*ALD*2)        // 18432
#define OFF_KHI (OFF_QLO + TQ*ALD*2)        // 36864
#define OFF_KLO (OFF_KHI + 64*ALD*2)        // 46080
#define OFF_VHI (OFF_KLO + 64*ALD*2)        // 55296
#define OFF_VLO (OFF_VHI + 64*ALD*2)        // 64512
#define OFF_PHI (OFF_VLO + 64*ALD*2)        // 73728
#define OFF_PLO (OFF_PHI + TQ*ALD*2)        // 92160
#define OFF_S   (OFF_PLO + TQ*ALD*2)        // 110592
#define OFF_L   (OFF_S + TQ*SLD*4)          // 145408
#define ATTN_SMEM (OFF_L + TQ*4)            // 145920

__global__ __launch_bounds__(256) void attn_wmma(float* __restrict__ out) {
    extern __shared__ __align__(128) char smraw[];
    __nv_bfloat16* Qhi_s = (__nv_bfloat16*)(smraw + OFF_QHI);
    __nv_bfloat16* Qlo_s = (__nv_bfloat16*)(smraw + OFF_QLO);
    __nv_bfloat16* Khi_s = (__nv_bfloat16*)(smraw + OFF_KHI);
    __nv_bfloat16* Klo_s = (__nv_bfloat16*)(smraw + OFF_KLO);
    __nv_bfloat16* Vhi_s = (__nv_bfloat16*)(smraw + OFF_VHI);
    __nv_bfloat16* Vlo_s = (__nv_bfloat16*)(smraw + OFF_VLO);
    __nv_bfloat16* Phi_s = (__nv_bfloat16*)(smraw + OFF_PHI);
    __nv_bfloat16* Plo_s = (__nv_bfloat16*)(smraw + OFF_PLO);
    float* Ssh = (float*)(smraw + OFF_S);
    float* Lsh = (float*)(smraw + OFF_L);

    int tid = threadIdx.x, wid = tid >> 5;
    int q0 = blockIdx.x * TQ, bh = blockIdx.y;
    int b = bh >> 4, h = bh & 15;

    const __nv_bfloat16* Qh = g_Qhi + ((size_t)bh * SEQ + q0) * HD;
    const __nv_bfloat16* Ql = g_Qlo + ((size_t)bh * SEQ + q0) * HD;
    const __nv_bfloat16* Kh = g_Khi + (size_t)bh * SEQ * HD;
    const __nv_bfloat16* Kl = g_Klo + (size_t)bh * SEQ * HD;
    const __nv_bfloat16* Vh = g_Vhi + (size_t)bh * SEQ * HD;
    const __nv_bfloat16* Vl = g_Vlo + (size_t)bh * SEQ * HD;

    // load Q tile (128 rows x 64 cols, hi/lo)
    #pragma unroll
    for (int i = 0; i < 4; i++) {
        int idx = tid + i * 256;         // 0..1023
        int row = idx >> 3, c8 = (idx & 7) * 8;
        *(uint4*)&Qhi_s[row * ALD + c8] = *(const uint4*)&Qh[row * HD + c8];
        *(uint4*)&Qlo_s[row * ALD + c8] = *(const uint4*)&Ql[row * HD + c8];
    }
    if (tid < TQ) Lsh[tid] = 0.f;

    int wm = (wid >> 1) * 32, wn = (wid & 1) * 32;
    wmma::fragment<wmma::accumulator, 16, 16, 16, float> ctx[2][2];
    #pragma unroll
    for (int i = 0; i < 2; i++)
        #pragma unroll
        for (int j = 0; j < 2; j++) wmma::fill_fragment(ctx[i][j], 0.f);

    for (int kt = 0; kt < SEQ / 64; kt++) {
        __syncthreads();
        #pragma unroll
        for (int i = 0; i < 2; i++) {
            int idx = tid + i * 256;     // 0..511
            int row = idx >> 3, c8 = (idx & 7) * 8;
            size_t g = (size_t)(kt * 64 + row) * HD + c8;
            *(uint4*)&Khi_s[row * ALD + c8] = *(const uint4*)&Kh[g];
            *(uint4*)&Klo_s[row * ALD + c8] = *(const uint4*)&Kl[g];
            *(uint4*)&Vhi_s[row * ALD + c8] = *(const uint4*)&Vh[g];
            *(uint4*)&Vlo_s[row * ALD + c8] = *(const uint4*)&Vl[g];
        }
        __syncthreads();

        // S = Q . K^T  (hi*hi + hi*lo + lo*hi)
        wmma::fragment<wmma::accumulator, 16, 16, 16, float> sc[2][2];
        #pragma unroll
        for (int i = 0; i < 2; i++)
            #pragma unroll
            for (int j = 0; j < 2; j++) wmma::fill_fragment(sc[i][j], 0.f);
        #pragma unroll
        for (int ks = 0; ks < 4; ks++) {
            wmma::fragment<wmma::matrix_a, 16, 16, 16, __nv_bfloat16, wmma::row_major> ah[2], al[2];
            wmma::fragment<wmma::matrix_b, 16, 16, 16, __nv_bfloat16, wmma::col_major> bhf[2], blf[2];
            #pragma unroll
            for (int i = 0; i < 2; i++) {
                wmma::load_matrix_sync(ah[i], &Qhi_s[(wm + 16 * i) * ALD + 16 * ks], ALD);
                wmma::load_matrix_sync(al[i], &Qlo_s[(wm + 16 * i) * ALD + 16 * ks], ALD);
            }
            #pragma unroll
            for (int j = 0; j < 2; j++) {
                wmma::load_matrix_sync(bhf[j], &Khi_s[(wn + 16 * j) * ALD + 16 * ks], ALD);
                wmma::load_matrix_sync(blf[j], &Klo_s[(wn + 16 * j) * ALD + 16 * ks], ALD);
            }
            #pragma unroll
            for (int i = 0; i < 2; i++)
                #pragma unroll
                for (int j = 0; j < 2; j++) {
                    wmma::mma_sync(sc[i][j], ah[i], bhf[j], sc[i][j]);
                    wmma::mma_sync(sc[i][j], ah[i], blf[j], sc[i][j]);
                    wmma::mma_sync(sc[i][j], al[i], bhf[j], sc[i][j]);
                }
        }
        #pragma unroll
        for (int i = 0; i < 2; i++)
            #pragma unroll
            for (int j = 0; j < 2; j++)
                wmma::store_matrix_sync(&Ssh[(wm + 16 * i) * SLD + wn + 16 * j],
                                        sc[i][j], SLD, wmma::mem_row_major);
        __syncthreads();

        // exp (unnormalized) + row sums; split P to bf16 hi/lo
        {
            int r = tid >> 1, c0 = (tid & 1) * 32;
            float sum = 0.f;
            #pragma unroll
            for (int cc = 0; cc < 32; cc++) {
                float p = expf(Ssh[r * SLD + c0 + cc] * SCALE);
                sum += p;
                __nv_bfloat16 hv = __float2bfloat16(p);
                Phi_s[r * ALD + c0 + cc] = hv;
                Plo_s[r * ALD + c0 + cc] = __float2bfloat16(p - __bfloat162float(hv));
            }
            sum += __shfl_xor_sync(0xffffffffu, sum, 1);
            if ((tid & 1) == 0) Lsh[r] += sum;
        }
        __syncthreads();

        // ctx += P . V  (Ph.Vh + Ph.Vl + Pl.Vh)
        #pragma unroll
        for (int ks = 0; ks < 4; ks++) {
            wmma::fragment<wmma::matrix_a, 16, 16, 16, __nv_bfloat16, wmma::row_major> ah[2], al[2];
            wmma::fragment<wmma::matrix_b, 16, 16, 16, __nv_bfloat16, wmma::row_major> bhf[2], blf[2];
            #pragma unroll
            for (int i = 0; i < 2; i++) {
                wmma::load_matrix_sync(ah[i], &Phi_s[(wm + 16 * i) * ALD + 16 * ks], ALD);
                wmma::load_matrix_sync(al[i], &Plo_s[(wm + 16 * i) * ALD + 16 * ks], ALD);
            }
            #pragma unroll
            for (int j = 0; j < 2; j++) {
                wmma::load_matrix_sync(bhf[j], &Vhi_s[16 * ks * ALD + wn + 16 * j], ALD);
                wmma::load_matrix_sync(blf[j], &Vlo_s[16 * ks * ALD + wn + 16 * j], ALD);
            }
            #pragma unroll
            for (int i = 0; i < 2; i++)
                #pragma unroll
                for (int j = 0; j < 2; j++) {
                    wmma::mma_sync(ctx[i][j], ah[i], bhf[j], ctx[i][j]);
                    wmma::mma_sync(ctx[i][j], ah[i], blf[j], ctx[i][j]);
                    wmma::mma_sync(ctx[i][j], al[i], bhf[j], ctx[i][j]);
                }
        }
    }
    __syncthreads();
    #pragma unroll
    for (int i = 0; i < 2; i++)
        #pragma unroll
        for (int j = 0; j < 2; j++)
            wmma::store_matrix_sync(&Ssh[(wm + 16 * i) * SLD + wn + 16 * j],
                                    ctx[i][j], SLD, wmma::mem_row_major);
    __syncthreads();

    {
        int r = tid >> 1, c0 = (tid & 1) * 32;
        float linv = 1.f / Lsh[r];
        int s = q0 + r;
        float* dst = out + ((size_t)b * SEQ + s) * DIM + h * HD + c0;
        #pragma unroll
        for (int cc = 0; cc < 32; cc += 4) {
            float4 v;
            v.x = Ssh[r * SLD + c0 + cc]     * linv;
            v.y = Ssh[r * SLD + c0 + cc + 1] * linv;
            v.z = Ssh[r * SLD + c0 + cc + 2] * linv;
            v.w = Ssh[r * SLD + c0 + cc + 3] * linv;
            *(float4*)(dst + cc) = v;
        }
    }
}

// ---------------------------------------------------------------------------
extern "C" void kernel_launch(void* const* d_in, const int* in_sizes, int n_in,
                              void* d_out, int out_size) {
    const float* X  = (const float*)d_in[0];
    const float* Wq = (const float*)d_in[1];
    const float* bq = (const float*)d_in[2];
    const float* Wk = (const float*)d_in[3];
    const float* bk = (const float*)d_in[4];
    const float* Wv = (const float*)d_in[5];
    const float* bv = (const float*)d_in[6];
    float* out = (float*)d_out;

    rope_table_kernel<<<(SEQ * DH + 255) / 256, 256>>>();

    split_kernel<<<(MTOT * DIM / 2 + 255) / 256, 256>>>(X, 0, MTOT * DIM / 2);
    split_kernel<<<(DIM * DIM / 2 + 255) / 256, 256>>>(Wq, 1, DIM * DIM / 2);
    split_kernel<<<(DIM * DIM / 2 + 255) / 256, 256>>>(Wk, 2, DIM * DIM / 2);
    split_kernel<<<(DIM * DIM / 2 + 255) / 256, 256>>>(Wv, 3, DIM * DIM / 2);

    cudaFuncSetAttribute(gemm_wmma, cudaFuncAttributeMaxDynamicSharedMemorySize, PROJ_SMEM);
    dim3 ggrid(DIM / 128, MTOT / 128, 3);
    gemm_wmma<<<ggrid, 256, PROJ_SMEM>>>();

    dim3 fgrid(MTOT * 16 * 8 / 256, 1, 3);
    finish_kernel<<<fgrid, 256>>>(bq, bk, bv);

    cudaFuncSetAttribute(attn_wmma, cudaFuncAttributeMaxDynamicSharedMemorySize, ATTN_SMEM);
    dim3 agrid(SEQ / TQ, BATCH * NH);
    attn_wmma<<<agrid, 256, ATTN_SMEM>>>(out);
}

// round 9
// speedup vs baseline: 3.0431x; 1.4020x over previous
#include <cuda_runtime.h>
#include <cuda_bf16.h>
#include <cuda_fp16.h>
#include <mma.h>
#include <math.h>
#include <stdint.h>

using namespace nvcuda;

#define BATCH 2
#define SEQ 2048
#define DIM 1024
#define NH 16
#define HD 64
#define DH 32
#define MTOT (BATCH*SEQ)   // 4096
#define SCALE 0.125f

// ---------------- device scratch (no allocation allowed) -------------------
__device__ float g_Y[3][MTOT*DIM];
__device__ float g_sin[SEQ*DH], g_cos[SEQ*DH];
__device__ __nv_bfloat16 g_Xhi[MTOT*DIM], g_Xlo[MTOT*DIM];
__device__ __nv_bfloat16 g_Whi[3][DIM*DIM], g_Wlo[3][DIM*DIM];
__device__ __nv_bfloat16 g_Qhi[MTOT*DIM], g_Qlo[MTOT*DIM];
__device__ __nv_bfloat16 g_Khi[MTOT*DIM], g_Klo[MTOT*DIM];
__device__ __half g_Vhalf[MTOT*DIM];

// ---------------------------------------------------------------------------
// RoPE tables in double precision (safe at large angles)
// ---------------------------------------------------------------------------
__global__ void rope_table_kernel() {
    int idx = blockIdx.x * blockDim.x + threadIdx.x;
    if (idx >= SEQ * DH) return;
    int s = idx / DH, i = idx % DH;
    double ang = (double)s * pow(10000.0, -((double)i) / (double)DH);
    g_sin[idx] = (float)sin(ang);
    g_cos[idx] = (float)cos(ang);
}

// ---------------------------------------------------------------------------
// Split fp32 -> bf16 hi + bf16 lo.  which: 0=X, 1..3=W[0..2]
// ---------------------------------------------------------------------------
__global__ void split_kernel(const float* __restrict__ src, int which, int n2) {
    __nv_bfloat16* hi = (which == 0) ? g_Xhi : g_Whi[which - 1];
    __nv_bfloat16* lo = (which == 0) ? g_Xlo : g_Wlo[which - 1];
    int i = blockIdx.x * blockDim.x + threadIdx.x;
    if (i >= n2) return;
    float2 x = ((const float2*)src)[i];
    float h0 = __bfloat162float(__float2bfloat16(x.x));
    float h1 = __bfloat162float(__float2bfloat16(x.y));
    __nv_bfloat162 hh, ll;
    hh.x = __float2bfloat16(h0);
    hh.y = __float2bfloat16(h1);
    ll.x = __float2bfloat16(x.x - h0);
    ll.y = __float2bfloat16(x.y - h1);
    ((__nv_bfloat162*)hi)[i] = hh;
    ((__nv_bfloat162*)lo)[i] = ll;
}

// ---------------------------------------------------------------------------
// WMMA GEMM: g_Y[which] = X @ W[which]^T  (bf16 hi/lo split, 3 MMAs).
// Tile 128x128, 8 warps (2m x 4n), k-chunk 64.
// ---------------------------------------------------------------------------
#define PLD 72      // bf16 smem ld for 64-wide k-chunk
#define PROJ_SMEM (4 * 128 * PLD * 2)   // 73728 bytes

__global__ __launch_bounds__(256) void gemm_wmma() {
    extern __shared__ __align__(128) char smraw[];
    __nv_bfloat16* Ahi = (__nv_bfloat16*)smraw;
    __nv_bfloat16* Alo = Ahi + 128 * PLD;
    __nv_bfloat16* Bhi = Alo + 128 * PLD;
    __nv_bfloat16* Blo = Bhi + 128 * PLD;

    int tid = threadIdx.x, wid = tid >> 5;
    int n0 = blockIdx.x * 128, m0 = blockIdx.y * 128, which = blockIdx.z;

    const __nv_bfloat16* Xh = g_Xhi + (size_t)m0 * DIM;
    const __nv_bfloat16* Xl = g_Xlo + (size_t)m0 * DIM;
    const __nv_bfloat16* Wh = g_Whi[which] + (size_t)n0 * DIM;
    const __nv_bfloat16* Wl = g_Wlo[which] + (size_t)n0 * DIM;

    wmma::fragment<wmma::accumulator, 16, 16, 16, float> c[4][2];
    #pragma unroll
    for (int i = 0; i < 4; i++)
        #pragma unroll
        for (int j = 0; j < 2; j++) wmma::fill_fragment(c[i][j], 0.f);

    int wm = (wid >> 2) * 64, wn = (wid & 3) * 32;

    for (int k0 = 0; k0 < DIM; k0 += 64) {
        __syncthreads();
        #pragma unroll
        for (int i = 0; i < 4; i++) {
            int idx = tid + i * 256;         // 0..1023
            int row = idx >> 3, c8 = (idx & 7) * 8;
            *(uint4*)&Ahi[row * PLD + c8] = *(const uint4*)&Xh[row * DIM + k0 + c8];
            *(uint4*)&Alo[row * PLD + c8] = *(const uint4*)&Xl[row * DIM + k0 + c8];
            *(uint4*)&Bhi[row * PLD + c8] = *(const uint4*)&Wh[row * DIM + k0 + c8];
            *(uint4*)&Blo[row * PLD + c8] = *(const uint4*)&Wl[row * DIM + k0 + c8];
        }
        __syncthreads();

        #pragma unroll
        for (int ks = 0; ks < 4; ks++) {
            wmma::fragment<wmma::matrix_a, 16, 16, 16, __nv_bfloat16, wmma::row_major> ah[4], al[4];
            wmma::fragment<wmma::matrix_b, 16, 16, 16, __nv_bfloat16, wmma::col_major> bh[2], bl[2];
            #pragma unroll
            for (int i = 0; i < 4; i++) {
                wmma::load_matrix_sync(ah[i], &Ahi[(wm + 16 * i) * PLD + ks * 16], PLD);
                wmma::load_matrix_sync(al[i], &Alo[(wm + 16 * i) * PLD + ks * 16], PLD);
            }
            #pragma unroll
            for (int j = 0; j < 2; j++) {
                wmma::load_matrix_sync(bh[j], &Bhi[(wn + 16 * j) * PLD + ks * 16], PLD);
                wmma::load_matrix_sync(bl[j], &Blo[(wn + 16 * j) * PLD + ks * 16], PLD);
            }
            #pragma unroll
            for (int i = 0; i < 4; i++)
                #pragma unroll
                for (int j = 0; j < 2; j++) {
                    wmma::mma_sync(c[i][j], ah[i], bh[j], c[i][j]);
                    wmma::mma_sync(c[i][j], ah[i], bl[j], c[i][j]);
                    wmma::mma_sync(c[i][j], al[i], bh[j], c[i][j]);
                }
        }
    }

    float* Y = g_Y[which];
    #pragma unroll
    for (int i = 0; i < 4; i++)
        #pragma unroll
        for (int j = 0; j < 2; j++)
            wmma::store_matrix_sync(&Y[(size_t)(m0 + wm + 16 * i) * DIM + n0 + wn + 16 * j],
                                    c[i][j], DIM, wmma::mem_row_major);
}

// ---------------------------------------------------------------------------
// finish: bias + RoPE + transpose.
// Q,K -> bf16 hi/lo.  V -> fp16 single (enters output linearly; fp16's 11-bit
// mantissa keeps its contribution ~3e-4).
// ---------------------------------------------------------------------------
__global__ __launch_bounds__(256) void finish_kernel(
    const float* __restrict__ bq, const float* __restrict__ bk,
    const float* __restrict__ bv)
{
    int which = blockIdx.z;
    int gidx = blockIdx.x * 256 + threadIdx.x;   // 0 .. MTOT*16*8-1
    int q = gidx & 7;
    int h = (gidx >> 3) & 15;
    int m = gidx >> 7;
    int b = m / SEQ, s = m % SEQ;
    int c0 = q * 4;

    const float* Yrow = g_Y[which] + (size_t)m * DIM + h * HD;
    const float* bias = (which == 0) ? bq : (which == 1) ? bk : bv;

    float4 x1 = *(const float4*)(Yrow + c0);
    float4 x2 = *(const float4*)(Yrow + c0 + DH);
    x1.x += bias[h * HD + c0];     x1.y += bias[h * HD + c0 + 1];
    x1.z += bias[h * HD + c0 + 2]; x1.w += bias[h * HD + c0 + 3];
    x2.x += bias[h * HD + c0 + DH];     x2.y += bias[h * HD + c0 + DH + 1];
    x2.z += bias[h * HD + c0 + DH + 2]; x2.w += bias[h * HD + c0 + DH + 3];

    float o1[4] = {x1.x, x1.y, x1.z, x1.w};
    float o2[4] = {x2.x, x2.y, x2.z, x2.w};
    size_t base = ((size_t)(b * NH + h) * SEQ + s) * HD;

    if (which == 2) {
        // V: fp16 single buffer
        #pragma unroll
        for (int half_i = 0; half_i < 2; half_i++) {
            float* o = half_i ? o2 : o1;
            size_t off = base + c0 + half_i * DH;
            __half2 v0, v1;
            v0.x = __float2half(o[0]); v0.y = __float2half(o[1]);
            v1.x = __float2half(o[2]); v1.y = __float2half(o[3]);
            *(__half2*)(g_Vhalf + off)     = v0;
            *(__half2*)(g_Vhalf + off + 2) = v1;
        }
        return;
    }

    #pragma unroll
    for (int t = 0; t < 4; t++) {
        float sn = g_sin[s * DH + c0 + t], cs = g_cos[s * DH + c0 + t];
        float a = o1[t], bb = o2[t];
        o1[t] = a * cs - bb * sn;
        o2[t] = a * sn + bb * cs;
    }
    __nv_bfloat16* ph = (which == 0) ? g_Qhi : g_Khi;
    __nv_bfloat16* pl = (which == 0) ? g_Qlo : g_Klo;
    #pragma unroll
    for (int half_i = 0; half_i < 2; half_i++) {
        float* o = half_i ? o2 : o1;
        size_t off = base + c0 + half_i * DH;
        __nv_bfloat162 hh0, hh1, ll0, ll1;
        hh0.x = __float2bfloat16(o[0]); hh0.y = __float2bfloat16(o[1]);
        hh1.x = __float2bfloat16(o[2]); hh1.y = __float2bfloat16(o[3]);
        ll0.x = __float2bfloat16(o[0] - __bfloat162float(hh0.x));
        ll0.y = __float2bfloat16(o[1] - __bfloat162float(hh0.y));
        ll1.x = __float2bfloat16(o[2] - __bfloat162float(hh1.x));
        ll1.y = __float2bfloat16(o[3] - __bfloat162float(hh1.y));
        *(__nv_bfloat162*)(ph + off)     = hh0;
        *(__nv_bfloat162*)(ph + off + 2) = hh1;
        *(__nv_bfloat162*)(pl + off)     = ll0;
        *(__nv_bfloat162*)(pl + off + 2) = ll1;
    }
}

// ---------------------------------------------------------------------------
// WMMA flash attention: 128q x 64k tiles, 8 warps (4m x 2n), 256 threads.
// QK^T: bf16 hi/lo, 3 MMAs (exp amplifies score errors).
// P.V:  SINGLE fp16 MMA (11-bit mantissa -> ~3e-4 contribution).
// Unnormalized exp + running row-sum; divide at the end. No smem overlays.
// ---------------------------------------------------------------------------
#define TQ 128
#define ALD 72      // 16-bit smem ld
#define SLD 68      // fp32 smem ld
#define OFF_QHI 0
#define OFF_QLO (OFF_QHI + TQ*ALD*2)        // 18432
#define OFF_KHI (OFF_QLO + TQ*ALD*2)        // 36864
#define OFF_KLO (OFF_KHI + 64*ALD*2)        // 46080
#define OFF_VH  (OFF_KLO + 64*ALD*2)        // 55296  (fp16)
#define OFF_PH  (OFF_VH + 64*ALD*2)         // 64512  (fp16)
#define OFF_S   (OFF_PH + TQ*ALD*2)         // 82944
#define OFF_L   (OFF_S + TQ*SLD*4)          // 117760
#define ATTN_SMEM (OFF_L + TQ*4)            // 118272

__global__ __launch_bounds__(256) void attn_wmma(float* __restrict__ out) {
    extern __shared__ __align__(128) char smraw[];
    __nv_bfloat16* Qhi_s = (__nv_bfloat16*)(smraw + OFF_QHI);
    __nv_bfloat16* Qlo_s = (__nv_bfloat16*)(smraw + OFF_QLO);
    __nv_bfloat16* Khi_s = (__nv_bfloat16*)(smraw + OFF_KHI);
    __nv_bfloat16* Klo_s = (__nv_bfloat16*)(smraw + OFF_KLO);
    __half*        Vh_s  = (__half*)(smraw + OFF_VH);
    __half*        Ph_s  = (__half*)(smraw + OFF_PH);
    float* Ssh = (float*)(smraw + OFF_S);
    float* Lsh = (float*)(smraw + OFF_L);

    int tid = threadIdx.x, wid = tid >> 5;
    int q0 = blockIdx.x * TQ, bh = blockIdx.y;
    int b = bh >> 4, h = bh & 15;

    const __nv_bfloat16* Qh = g_Qhi + ((size_t)bh * SEQ + q0) * HD;
    const __nv_bfloat16* Ql = g_Qlo + ((size_t)bh * SEQ + q0) * HD;
    const __nv_bfloat16* Kh = g_Khi + (size_t)bh * SEQ * HD;
    const __nv_bfloat16* Kl = g_Klo + (size_t)bh * SEQ * HD;
    const __half*        Vv = g_Vhalf + (size_t)bh * SEQ * HD;

    // load Q tile (128 rows x 64 cols, hi/lo)
    #pragma unroll
    for (int i = 0; i < 4; i++) {
        int idx = tid + i * 256;         // 0..1023
        int row = idx >> 3, c8 = (idx & 7) * 8;
        *(uint4*)&Qhi_s[row * ALD + c8] = *(const uint4*)&Qh[row * HD + c8];
        *(uint4*)&Qlo_s[row * ALD + c8] = *(const uint4*)&Ql[row * HD + c8];
    }
    if (tid < TQ) Lsh[tid] = 0.f;

    int wm = (wid >> 1) * 32, wn = (wid & 1) * 32;
    wmma::fragment<wmma::accumulator, 16, 16, 16, float> ctx[2][2];
    #pragma unroll
    for (int i = 0; i < 2; i++)
        #pragma unroll
        for (int j = 0; j < 2; j++) wmma::fill_fragment(ctx[i][j], 0.f);

    for (int kt = 0; kt < SEQ / 64; kt++) {
        __syncthreads();
        #pragma unroll
        for (int i = 0; i < 2; i++) {
            int idx = tid + i * 256;     // 0..511
            int row = idx >> 3, c8 = (idx & 7) * 8;
            size_t g = (size_t)(kt * 64 + row) * HD + c8;
            *(uint4*)&Khi_s[row * ALD + c8] = *(const uint4*)&Kh[g];
            *(uint4*)&Klo_s[row * ALD + c8] = *(const uint4*)&Kl[g];
            *(uint4*)&Vh_s[row * ALD + c8]  = *(const uint4*)&Vv[g];
        }
        __syncthreads();

        // S = Q . K^T  (hi*hi + hi*lo + lo*hi)
        wmma::fragment<wmma::accumulator, 16, 16, 16, float> sc[2][2];
        #pragma unroll
        for (int i = 0; i < 2; i++)
            #pragma unroll
            for (int j = 0; j < 2; j++) wmma::fill_fragment(sc[i][j], 0.f);
        #pragma unroll
        for (int ks = 0; ks < 4; ks++) {
            wmma::fragment<wmma::matrix_a, 16, 16, 16, __nv_bfloat16, wmma::row_major> ah[2], al[2];
            wmma::fragment<wmma::matrix_b, 16, 16, 16, __nv_bfloat16, wmma::col_major> bhf[2], blf[2];
            #pragma unroll
            for (int i = 0; i < 2; i++) {
                wmma::load_matrix_sync(ah[i], &Qhi_s[(wm + 16 * i) * ALD + 16 * ks], ALD);
                wmma::load_matrix_sync(al[i], &Qlo_s[(wm + 16 * i) * ALD + 16 * ks], ALD);
            }
            #pragma unroll
            for (int j = 0; j < 2; j++) {
                wmma::load_matrix_sync(bhf[j], &Khi_s[(wn + 16 * j) * ALD + 16 * ks], ALD);
                wmma::load_matrix_sync(blf[j], &Klo_s[(wn + 16 * j) * ALD + 16 * ks], ALD);
            }
            #pragma unroll
            for (int i = 0; i < 2; i++)
                #pragma unroll
                for (int j = 0; j < 2; j++) {
                    wmma::mma_sync(sc[i][j], ah[i], bhf[j], sc[i][j]);
                    wmma::mma_sync(sc[i][j], ah[i], blf[j], sc[i][j]);
                    wmma::mma_sync(sc[i][j], al[i], bhf[j], sc[i][j]);
                }
        }
        #pragma unroll
        for (int i = 0; i < 2; i++)
            #pragma unroll
            for (int j = 0; j < 2; j++)
                wmma::store_matrix_sync(&Ssh[(wm + 16 * i) * SLD + wn + 16 * j],
                                        sc[i][j], SLD, wmma::mem_row_major);
        __syncthreads();

        // exp (unnormalized) + row sums; P as fp16
        {
            int r = tid >> 1, c0 = (tid & 1) * 32;
            float sum = 0.f;
            #pragma unroll
            for (int cc = 0; cc < 32; cc += 2) {
                float p0 = expf(Ssh[r * SLD + c0 + cc]     * SCALE);
                float p1 = expf(Ssh[r * SLD + c0 + cc + 1] * SCALE);
                sum += p0 + p1;
                __half2 pv;
                pv.x = __float2half(p0);
                pv.y = __float2half(p1);
                *(__half2*)&Ph_s[r * ALD + c0 + cc] = pv;
            }
            sum += __shfl_xor_sync(0xffffffffu, sum, 1);
            if ((tid & 1) == 0) Lsh[r] += sum;
        }
        __syncthreads();

        // ctx += P . V  (single fp16 MMA)
        #pragma unroll
        for (int ks = 0; ks < 4; ks++) {
            wmma::fragment<wmma::matrix_a, 16, 16, 16, __half, wmma::row_major> ah[2];
            wmma::fragment<wmma::matrix_b, 16, 16, 16, __half, wmma::row_major> bhf[2];
            #pragma unroll
            for (int i = 0; i < 2; i++)
                wmma::load_matrix_sync(ah[i], &Ph_s[(wm + 16 * i) * ALD + 16 * ks], ALD);
            #pragma unroll
            for (int j = 0; j < 2; j++)
                wmma::load_matrix_sync(bhf[j], &Vh_s[16 * ks * ALD + wn + 16 * j], ALD);
            #pragma unroll
            for (int i = 0; i < 2; i++)
                #pragma unroll
                for (int j = 0; j < 2; j++)
                    wmma::mma_sync(ctx[i][j], ah[i], bhf[j], ctx[i][j]);
        }
    }
    __syncthreads();
    #pragma unroll
    for (int i = 0; i < 2; i++)
        #pragma unroll
        for (int j = 0; j < 2; j++)
            wmma::store_matrix_sync(&Ssh[(wm + 16 * i) * SLD + wn + 16 * j],
                                    ctx[i][j], SLD, wmma::mem_row_major);
    __syncthreads();

    {
        int r = tid >> 1, c0 = (tid & 1) * 32;
        float linv = 1.f / Lsh[r];
        int s = q0 + r;
        float* dst = out + ((size_t)b * SEQ + s) * DIM + h * HD + c0;
        #pragma unroll
        for (int cc = 0; cc < 32; cc += 4) {
            float4 v;
            v.x = Ssh[r * SLD + c0 + cc]     * linv;
            v.y = Ssh[r * SLD + c0 + cc + 1] * linv;
            v.z = Ssh[r * SLD + c0 + cc + 2] * linv;
            v.w = Ssh[r * SLD + c0 + cc + 3] * linv;
            *(float4*)(dst + cc) = v;
        }
    }
}

// ---------------------------------------------------------------------------
extern "C" void kernel_launch(void* const* d_in, const int* in_sizes, int n_in,
                              void* d_out, int out_size) {
    const float* X  = (const float*)d_in[0];
    const float* Wq = (const float*)d_in[1];
    const float* bq = (const float*)d_in[2];
    const float* Wk = (const float*)d_in[3];
    const float* bk = (const float*)d_in[4];
    const float* Wv = (const float*)d_in[5];
    const float* bv = (const float*)d_in[6];
    float* out = (float*)d_out;

    rope_table_kernel<<<(SEQ * DH + 255) / 256, 256>>>();

    split_kernel<<<(MTOT * DIM / 2 + 255) / 256, 256>>>(X, 0, MTOT * DIM / 2);
    split_kernel<<<(DIM * DIM / 2 + 255) / 256, 256>>>(Wq, 1, DIM * DIM / 2);
    split_kernel<<<(DIM * DIM / 2 + 255) / 256, 256>>>(Wk, 2, DIM * DIM / 2);
    split_kernel<<<(DIM * DIM / 2 + 255) / 256, 256>>>(Wv, 3, DIM * DIM / 2);

    cudaFuncSetAttribute(gemm_wmma, cudaFuncAttributeMaxDynamicSharedMemorySize, PROJ_SMEM);
    dim3 ggrid(DIM / 128, MTOT / 128, 3);
    gemm_wmma<<<ggrid, 256, PROJ_SMEM>>>();

    dim3 fgrid(MTOT * 16 * 8 / 256, 1, 3);
    finish_kernel<<<fgrid, 256>>>(bq, bk, bv);

    cudaFuncSetAttribute(attn_wmma, cudaFuncAttributeMaxDynamicSharedMemorySize, ATTN_SMEM);
    dim3 agrid(SEQ / TQ, BATCH * NH);
    attn_wmma<<<agrid, 256, ATTN_SMEM>>>(out);
}

// round 10
// speedup vs baseline: 5.2037x; 1.7100x over previous
#include <cuda_runtime.h>
#include <cuda_bf16.h>
#include <cuda_fp16.h>
#include <mma.h>
#include <math.h>
#include <stdint.h>

using namespace nvcuda;

#define BATCH 2
#define SEQ 2048
#define DIM 1024
#define NH 16
#define HD 64
#define DH 32
#define MTOT (BATCH*SEQ)   // 4096
#define SCALE 0.125f

// ---------------- device scratch (no allocation allowed) -------------------
__device__ float g_Y[3][MTOT*DIM];
__device__ float g_sin[SEQ*DH], g_cos[SEQ*DH];
__device__ __half g_Xhi[MTOT*DIM], g_Xlo[MTOT*DIM];   // X double-fp16 split
__device__ __half g_Wh[3][DIM*DIM];                   // W single fp16
__device__ __half g_Qh[MTOT*DIM];                     // Q single fp16
__device__ __half g_Kh[MTOT*DIM];                     // K single fp16
__device__ __half g_Vh[MTOT*DIM];                     // V single fp16

// ---------------------------------------------------------------------------
// RoPE tables in double precision (safe at large angles)
// ---------------------------------------------------------------------------
__global__ void rope_table_kernel() {
    int idx = blockIdx.x * blockDim.x + threadIdx.x;
    if (idx >= SEQ * DH) return;
    int s = idx / DH, i = idx % DH;
    double ang = (double)s * pow(10000.0, -((double)i) / (double)DH);
    g_sin[idx] = (float)sin(ang);
    g_cos[idx] = (float)cos(ang);
}

// ---------------------------------------------------------------------------
// Split/convert fp32 -> fp16.  which 0: X -> hi/lo double-fp16;
// which 1..3: W[which-1] -> single fp16.
// ---------------------------------------------------------------------------
__global__ void split_kernel(const float* __restrict__ src, int which, int n2) {
    int i = blockIdx.x * blockDim.x + threadIdx.x;
    if (i >= n2) return;
    float2 x = ((const float2*)src)[i];
    if (which == 0) {
        __half h0 = __float2half(x.x), h1 = __float2half(x.y);
        __half2 hh, ll;
        hh.x = h0; hh.y = h1;
        ll.x = __float2half(x.x - __half2float(h0));
        ll.y = __float2half(x.y - __half2float(h1));
        ((__half2*)g_Xhi)[i] = hh;
        ((__half2*)g_Xlo)[i] = ll;
    } else {
        __half2 hh;
        hh.x = __float2half(x.x);
        hh.y = __float2half(x.y);
        ((__half2*)g_Wh[which - 1])[i] = hh;
    }
}

// ---------------------------------------------------------------------------
// WMMA GEMM: g_Y[which] = X @ W[which]^T  (X hi/lo fp16, W single fp16: 2 MMAs)
// Tile 128x128, 8 warps (2m x 4n), k-chunk 64.
// ---------------------------------------------------------------------------
#define PLD 72      // fp16 smem ld for 64-wide k-chunk
#define PROJ_SMEM (3 * 128 * PLD * 2)   // 55296 bytes

__global__ __launch_bounds__(256) void gemm_wmma() {
    extern __shared__ __align__(128) char smraw[];
    __half* Ahi = (__half*)smraw;
    __half* Alo = Ahi + 128 * PLD;
    __half* Bh  = Alo + 128 * PLD;

    int tid = threadIdx.x, wid = tid >> 5;
    int n0 = blockIdx.x * 128, m0 = blockIdx.y * 128, which = blockIdx.z;

    const __half* Xh = g_Xhi + (size_t)m0 * DIM;
    const __half* Xl = g_Xlo + (size_t)m0 * DIM;
    const __half* Wp = g_Wh[which] + (size_t)n0 * DIM;

    wmma::fragment<wmma::accumulator, 16, 16, 16, float> c[4][2];
    #pragma unroll
    for (int i = 0; i < 4; i++)
        #pragma unroll
        for (int j = 0; j < 2; j++) wmma::fill_fragment(c[i][j], 0.f);

    int wm = (wid >> 2) * 64, wn = (wid & 3) * 32;

    for (int k0 = 0; k0 < DIM; k0 += 64) {
        __syncthreads();
        #pragma unroll
        for (int i = 0; i < 4; i++) {
            int idx = tid + i * 256;         // 0..1023
            int row = idx >> 3, c8 = (idx & 7) * 8;
            *(uint4*)&Ahi[row * PLD + c8] = *(const uint4*)&Xh[row * DIM + k0 + c8];
            *(uint4*)&Alo[row * PLD + c8] = *(const uint4*)&Xl[row * DIM + k0 + c8];
            *(uint4*)&Bh[row * PLD + c8]  = *(const uint4*)&Wp[row * DIM + k0 + c8];
        }
        __syncthreads();

        #pragma unroll
        for (int ks = 0; ks < 4; ks++) {
            wmma::fragment<wmma::matrix_a, 16, 16, 16, __half, wmma::row_major> ah[4], al[4];
            wmma::fragment<wmma::matrix_b, 16, 16, 16, __half, wmma::col_major> bf[2];
            #pragma unroll
            for (int i = 0; i < 4; i++) {
                wmma::load_matrix_sync(ah[i], &Ahi[(wm + 16 * i) * PLD + ks * 16], PLD);
                wmma::load_matrix_sync(al[i], &Alo[(wm + 16 * i) * PLD + ks * 16], PLD);
            }
            #pragma unroll
            for (int j = 0; j < 2; j++)
                wmma::load_matrix_sync(bf[j], &Bh[(wn + 16 * j) * PLD + ks * 16], PLD);
            #pragma unroll
            for (int i = 0; i < 4; i++)
                #pragma unroll
                for (int j = 0; j < 2; j++) {
                    wmma::mma_sync(c[i][j], ah[i], bf[j], c[i][j]);
                    wmma::mma_sync(c[i][j], al[i], bf[j], c[i][j]);
                }
        }
    }

    float* Y = g_Y[which];
    #pragma unroll
    for (int i = 0; i < 4; i++)
        #pragma unroll
        for (int j = 0; j < 2; j++)
            wmma::store_matrix_sync(&Y[(size_t)(m0 + wm + 16 * i) * DIM + n0 + wn + 16 * j],
                                    c[i][j], DIM, wmma::mem_row_major);
}

// ---------------------------------------------------------------------------
// finish: bias + RoPE + transpose  g_Y -> single fp16 Q/K/V [B,H,S,HD].
// ---------------------------------------------------------------------------
__global__ __launch_bounds__(256) void finish_kernel(
    const float* __restrict__ bq, const float* __restrict__ bk,
    const float* __restrict__ bv)
{
    int which = blockIdx.z;
    int gidx = blockIdx.x * 256 + threadIdx.x;   // 0 .. MTOT*16*8-1
    int q = gidx & 7;
    int h = (gidx >> 3) & 15;
    int m = gidx >> 7;
    int b = m / SEQ, s = m % SEQ;
    int c0 = q * 4;

    const float* Yrow = g_Y[which] + (size_t)m * DIM + h * HD;
    const float* bias = (which == 0) ? bq : (which == 1) ? bk : bv;

    float4 x1 = *(const float4*)(Yrow + c0);
    float4 x2 = *(const float4*)(Yrow + c0 + DH);
    x1.x += bias[h * HD + c0];     x1.y += bias[h * HD + c0 + 1];
    x1.z += bias[h * HD + c0 + 2]; x1.w += bias[h * HD + c0 + 3];
    x2.x += bias[h * HD + c0 + DH];     x2.y += bias[h * HD + c0 + DH + 1];
    x2.z += bias[h * HD + c0 + DH + 2]; x2.w += bias[h * HD + c0 + DH + 3];

    float o1[4] = {x1.x, x1.y, x1.z, x1.w};
    float o2[4] = {x2.x, x2.y, x2.z, x2.w};

    if (which != 2) {
        #pragma unroll
        for (int t = 0; t < 4; t++) {
            float sn = g_sin[s * DH + c0 + t], cs = g_cos[s * DH + c0 + t];
            float a = o1[t], bb = o2[t];
            o1[t] = a * cs - bb * sn;
            o2[t] = a * sn + bb * cs;
        }
    }
    __half* dstp = (which == 0) ? g_Qh : (which == 1) ? g_Kh : g_Vh;
    size_t base = ((size_t)(b * NH + h) * SEQ + s) * HD;
    #pragma unroll
    for (int half_i = 0; half_i < 2; half_i++) {
        float* o = half_i ? o2 : o1;
        size_t off = base + c0 + half_i * DH;
        __half2 v0, v1;
        v0.x = __float2half(o[0]); v0.y = __float2half(o[1]);
        v1.x = __float2half(o[2]); v1.y = __float2half(o[3]);
        *(__half2*)(dstp + off)     = v0;
        *(__half2*)(dstp + off + 2) = v1;
    }
}

// ---------------------------------------------------------------------------
// WMMA flash attention: 128q x 64k tiles, 8 warps (4m x 2n), 256 threads.
// QK^T: single fp16 MMA.  P.V: single fp16 MMA.
// Unnormalized exp + running row-sum; divide at the end. No smem overlays.
// smem ~90.6KB -> 2 CTAs/SM.
// ---------------------------------------------------------------------------
#define TQ 128
#define ALD 72      // fp16 smem ld
#define SLD 68      // fp32 smem ld
#define OFF_QH 0
#define OFF_KH (OFF_QH + TQ*ALD*2)         // 18432
#define OFF_VH (OFF_KH + 64*ALD*2)         // 27648
#define OFF_PH (OFF_VH + 64*ALD*2)         // 36864
#define OFF_S  (OFF_PH + TQ*ALD*2)         // 55296
#define OFF_L  (OFF_S + TQ*SLD*4)          // 90112
#define ATTN_SMEM (OFF_L + TQ*4)           // 90624

__global__ __launch_bounds__(256) void attn_wmma(float* __restrict__ out) {
    extern __shared__ __align__(128) char smraw[];
    __half* Qh_s = (__half*)(smraw + OFF_QH);
    __half* Kh_s = (__half*)(smraw + OFF_KH);
    __half* Vh_s = (__half*)(smraw + OFF_VH);
    __half* Ph_s = (__half*)(smraw + OFF_PH);
    float* Ssh = (float*)(smraw + OFF_S);
    float* Lsh = (float*)(smraw + OFF_L);

    int tid = threadIdx.x, wid = tid >> 5;
    int q0 = blockIdx.x * TQ, bh = blockIdx.y;
    int b = bh >> 4, h = bh & 15;

    const __half* Qp = g_Qh + ((size_t)bh * SEQ + q0) * HD;
    const __half* Kp = g_Kh + (size_t)bh * SEQ * HD;
    const __half* Vp = g_Vh + (size_t)bh * SEQ * HD;

    // load Q tile (128 rows x 64 cols fp16)
    #pragma unroll
    for (int i = 0; i < 4; i++) {
        int idx = tid + i * 256;         // 0..1023
        int row = idx >> 3, c8 = (idx & 7) * 8;
        *(uint4*)&Qh_s[row * ALD + c8] = *(const uint4*)&Qp[row * HD + c8];
    }
    if (tid < TQ) Lsh[tid] = 0.f;

    int wm = (wid >> 1) * 32, wn = (wid & 1) * 32;
    wmma::fragment<wmma::accumulator, 16, 16, 16, float> ctx[2][2];
    #pragma unroll
    for (int i = 0; i < 2; i++)
        #pragma unroll
        for (int j = 0; j < 2; j++) wmma::fill_fragment(ctx[i][j], 0.f);

    for (int kt = 0; kt < SEQ / 64; kt++) {
        __syncthreads();
        #pragma unroll
        for (int i = 0; i < 2; i++) {
            int idx = tid + i * 256;     // 0..511
            int row = idx >> 3, c8 = (idx & 7) * 8;
            size_t g = (size_t)(kt * 64 + row) * HD + c8;
            *(uint4*)&Kh_s[row * ALD + c8] = *(const uint4*)&Kp[g];
            *(uint4*)&Vh_s[row * ALD + c8] = *(const uint4*)&Vp[g];
        }
        __syncthreads();

        // S = Q . K^T  (single fp16 MMA)
        wmma::fragment<wmma::accumulator, 16, 16, 16, float> sc[2][2];
        #pragma unroll
        for (int i = 0; i < 2; i++)
            #pragma unroll
            for (int j = 0; j < 2; j++) wmma::fill_fragment(sc[i][j], 0.f);
        #pragma unroll
        for (int ks = 0; ks < 4; ks++) {
            wmma::fragment<wmma::matrix_a, 16, 16, 16, __half, wmma::row_major> af[2];
            wmma::fragment<wmma::matrix_b, 16, 16, 16, __half, wmma::col_major> bf[2];
            #pragma unroll
            for (int i = 0; i < 2; i++)
                wmma::load_matrix_sync(af[i], &Qh_s[(wm + 16 * i) * ALD + 16 * ks], ALD);
            #pragma unroll
            for (int j = 0; j < 2; j++)
                wmma::load_matrix_sync(bf[j], &Kh_s[(wn + 16 * j) * ALD + 16 * ks], ALD);
            #pragma unroll
            for (int i = 0; i < 2; i++)
                #pragma unroll
                for (int j = 0; j < 2; j++)
                    wmma::mma_sync(sc[i][j], af[i], bf[j], sc[i][j]);
        }
        #pragma unroll
        for (int i = 0; i < 2; i++)
            #pragma unroll
            for (int j = 0; j < 2; j++)
                wmma::store_matrix_sync(&Ssh[(wm + 16 * i) * SLD + wn + 16 * j],
                                        sc[i][j], SLD, wmma::mem_row_major);
        __syncthreads();

        // exp (unnormalized) + row sums; P as fp16
        {
            int r = tid >> 1, c0 = (tid & 1) * 32;
            float sum = 0.f;
            #pragma unroll
            for (int cc = 0; cc < 32; cc += 2) {
                float p0 = expf(Ssh[r * SLD + c0 + cc]     * SCALE);
                float p1 = expf(Ssh[r * SLD + c0 + cc + 1] * SCALE);
                sum += p0 + p1;
                __half2 pv;
                pv.x = __float2half(p0);
                pv.y = __float2half(p1);
                *(__half2*)&Ph_s[r * ALD + c0 + cc] = pv;
            }
            sum += __shfl_xor_sync(0xffffffffu, sum, 1);
            if ((tid & 1) == 0) Lsh[r] += sum;
        }
        __syncthreads();

        // ctx += P . V  (single fp16 MMA)
        #pragma unroll
        for (int ks = 0; ks < 4; ks++) {
            wmma::fragment<wmma::matrix_a, 16, 16, 16, __half, wmma::row_major> af[2];
            wmma::fragment<wmma::matrix_b, 16, 16, 16, __half, wmma::row_major> bf[2];
            #pragma unroll
            for (int i = 0; i < 2; i++)
                wmma::load_matrix_sync(af[i], &Ph_s[(wm + 16 * i) * ALD + 16 * ks], ALD);
            #pragma unroll
            for (int j = 0; j < 2; j++)
                wmma::load_matrix_sync(bf[j], &Vh_s[16 * ks * ALD + wn + 16 * j], ALD);
            #pragma unroll
            for (int i = 0; i < 2; i++)
                #pragma unroll
                for (int j = 0; j < 2; j++)
                    wmma::mma_sync(ctx[i][j], af[i], bf[j], ctx[i][j]);
        }
    }
    __syncthreads();
    #pragma unroll
    for (int i = 0; i < 2; i++)
        #pragma unroll
        for (int j = 0; j < 2; j++)
            wmma::store_matrix_sync(&Ssh[(wm + 16 * i) * SLD + wn + 16 * j],
                                    ctx[i][j], SLD, wmma::mem_row_major);
    __syncthreads();

    {
        int r = tid >> 1, c0 = (tid & 1) * 32;
        float linv = 1.f / Lsh[r];
        int s = q0 + r;
        float* dst = out + ((size_t)b * SEQ + s) * DIM + h * HD + c0;
        #pragma unroll
        for (int cc = 0; cc < 32; cc += 4) {
            float4 v;
            v.x = Ssh[r * SLD + c0 + cc]     * linv;
            v.y = Ssh[r * SLD + c0 + cc + 1] * linv;
            v.z = Ssh[r * SLD + c0 + cc + 2] * linv;
            v.w = Ssh[r * SLD + c0 + cc + 3] * linv;
            *(float4*)(dst + cc) = v;
        }
    }
}

// ---------------------------------------------------------------------------
extern "C" void kernel_launch(void* const* d_in, const int* in_sizes, int n_in,
                              void* d_out, int out_size) {
    const float* X  = (const float*)d_in[0];
    const float* Wq = (const float*)d_in[1];
    const float* bq = (const float*)d_in[2];
    const float* Wk = (const float*)d_in[3];
    const float* bk = (const float*)d_in[4];
    const float* Wv = (const float*)d_in[5];
    const float* bv = (const float*)d_in[6];
    float* out = (float*)d_out;

    rope_table_kernel<<<(SEQ * DH + 255) / 256, 256>>>();

    split_kernel<<<(MTOT * DIM / 2 + 255) / 256, 256>>>(X, 0, MTOT * DIM / 2);
    split_kernel<<<(DIM * DIM / 2 + 255) / 256, 256>>>(Wq, 1, DIM * DIM / 2);
    split_kernel<<<(DIM * DIM / 2 + 255) / 256, 256>>>(Wk, 2, DIM * DIM / 2);
    split_kernel<<<(DIM * DIM / 2 + 255) / 256, 256>>>(Wv, 3, DIM * DIM / 2);

    cudaFuncSetAttribute(gemm_wmma, cudaFuncAttributeMaxDynamicSharedMemorySize, PROJ_SMEM);
    dim3 ggrid(DIM / 128, MTOT / 128, 3);
    gemm_wmma<<<ggrid, 256, PROJ_SMEM>>>();

    dim3 fgrid(MTOT * 16 * 8 / 256, 1, 3);
    finish_kernel<<<fgrid, 256>>>(bq, bk, bv);

    cudaFuncSetAttribute(attn_wmma, cudaFuncAttributeMaxDynamicSharedMemorySize, ATTN_SMEM);
    dim3 agrid(SEQ / TQ, BATCH * NH);
    attn_wmma<<<agrid, 256, ATTN_SMEM>>>(out);
}

// round 11
// speedup vs baseline: 6.4726x; 1.2439x over previous
#include <cuda_runtime.h>
#include <cuda_fp16.h>
#include <mma.h>
#include <math.h>
#include <stdint.h>

using namespace nvcuda;

#define BATCH 2
#define SEQ 2048
#define DIM 1024
#define NH 16
#define HD 64
#define DH 32
#define MTOT (BATCH*SEQ)   // 4096
#define SCALE 0.125f

// ---------------- device scratch (no allocation allowed) -------------------
__device__ float g_sin[SEQ*DH], g_cos[SEQ*DH];
__device__ __half g_Xh[MTOT*DIM];
__device__ __half g_Wh[3][DIM*DIM];
__device__ __half g_Qh[MTOT*DIM];
__device__ __half g_Kh[MTOT*DIM];
__device__ __half g_Vh[MTOT*DIM];

// ---------------- cp.async helpers -----------------------------------------
#define CP_ASYNC16(dst_u32, src_ptr) \
    asm volatile("cp.async.cg.shared.global [%0], [%1], 16;" \
                 :: "r"(dst_u32), "l"(src_ptr) : "memory")
#define CP_COMMIT() asm volatile("cp.async.commit_group;" ::: "memory")
#define CP_WAIT0()  asm volatile("cp.async.wait_group 0;" ::: "memory")

// ---------------------------------------------------------------------------
// RoPE tables in double precision (safe at large angles)
// ---------------------------------------------------------------------------
__global__ void rope_table_kernel() {
    int idx = blockIdx.x * blockDim.x + threadIdx.x;
    if (idx >= SEQ * DH) return;
    int s = idx / DH, i = idx % DH;
    double ang = (double)s * pow(10000.0, -((double)i) / (double)DH);
    g_sin[idx] = (float)sin(ang);
    g_cos[idx] = (float)cos(ang);
}

// ---------------------------------------------------------------------------
// Convert fp32 -> single fp16.  which 0: X; 1..3: W[which-1]
// ---------------------------------------------------------------------------
__global__ void split_kernel(const float* __restrict__ src, int which, int n2) {
    int i = blockIdx.x * blockDim.x + threadIdx.x;
    if (i >= n2) return;
    float2 x = ((const float2*)src)[i];
    __half2 hh;
    hh.x = __float2half(x.x);
    hh.y = __float2half(x.y);
    __half* dst = (which == 0) ? g_Xh : g_Wh[which - 1];
    ((__half2*)dst)[i] = hh;
}

// ---------------------------------------------------------------------------
// Fused WMMA GEMM + epilogue: Q/K/V[which] = rope(X @ W^T + b) as fp16
// [B,H,S,HD].  Single fp16 MMA. Tile 128x128, 8 warps (2m x 4n), k-chunk 64.
// Accumulators -> DEDICATED fp32 smem region (disjoint from staging; no
// overlay/retyping) -> bias+RoPE+transpose -> fp16 global.
// ---------------------------------------------------------------------------
#define PLD 72                       // fp16 staging ld
#define YLD 132                      // fp32 epilogue ld (128 + 4 pad)
#define G_STAGE (2 * 128 * PLD * 2)  // 36864: A + B staging
#define PROJ_SMEM (G_STAGE + 128 * YLD * 4)   // 36864 + 67584 = 104448

__global__ __launch_bounds__(256) void gemm_fused(
    const float* __restrict__ bq, const float* __restrict__ bk,
    const float* __restrict__ bv)
{
    extern __shared__ __align__(128) char smraw[];
    __half* Ast = (__half*)smraw;
    __half* Bst = Ast + 128 * PLD;
    float*  Ysh = (float*)(smraw + G_STAGE);   // dedicated, disjoint

    int tid = threadIdx.x, wid = tid >> 5;
    int n0 = blockIdx.x * 128, m0 = blockIdx.y * 128, which = blockIdx.z;

    const __half* Xp = g_Xh + (size_t)m0 * DIM;
    const __half* Wp = g_Wh[which] + (size_t)n0 * DIM;

    wmma::fragment<wmma::accumulator, 16, 16, 16, float> c[4][2];
    #pragma unroll
    for (int i = 0; i < 4; i++)
        #pragma unroll
        for (int j = 0; j < 2; j++) wmma::fill_fragment(c[i][j], 0.f);

    int wm = (wid >> 2) * 64, wn = (wid & 3) * 32;

    for (int k0 = 0; k0 < DIM; k0 += 64) {
        __syncthreads();
        #pragma unroll
        for (int i = 0; i < 4; i++) {
            int idx = tid + i * 256;         // 0..1023
            int row = idx >> 3, c8 = (idx & 7) * 8;
            *(uint4*)&Ast[row * PLD + c8] = *(const uint4*)&Xp[row * DIM + k0 + c8];
            *(uint4*)&Bst[row * PLD + c8] = *(const uint4*)&Wp[row * DIM + k0 + c8];
        }
        __syncthreads();

        #pragma unroll
        for (int ks = 0; ks < 4; ks++) {
            wmma::fragment<wmma::matrix_a, 16, 16, 16, __half, wmma::row_major> af[4];
            wmma::fragment<wmma::matrix_b, 16, 16, 16, __half, wmma::col_major> bf[2];
            #pragma unroll
            for (int i = 0; i < 4; i++)
                wmma::load_matrix_sync(af[i], &Ast[(wm + 16 * i) * PLD + ks * 16], PLD);
            #pragma unroll
            for (int j = 0; j < 2; j++)
                wmma::load_matrix_sync(bf[j], &Bst[(wn + 16 * j) * PLD + ks * 16], PLD);
            #pragma unroll
            for (int i = 0; i < 4; i++)
                #pragma unroll
                for (int j = 0; j < 2; j++)
                    wmma::mma_sync(c[i][j], af[i], bf[j], c[i][j]);
        }
    }

    __syncthreads();
    #pragma unroll
    for (int i = 0; i < 4; i++)
        #pragma unroll
        for (int j = 0; j < 2; j++)
            wmma::store_matrix_sync(&Ysh[(wm + 16 * i) * YLD + wn + 16 * j],
                                    c[i][j], YLD, wmma::mem_row_major);
    __syncthreads();

    // Epilogue (identical math to the verified finish_kernel, reading smem)
    const float* bias = (which == 0) ? bq : (which == 1) ? bk : bv;
    __half* dstp = (which == 0) ? g_Qh : (which == 1) ? g_Kh : g_Vh;
    #pragma unroll
    for (int it = 0; it < 8; it++) {
        int idx = tid + it * 256;        // 0..2047
        int q = idx & 7;
        int hh = (idx >> 3) & 1;
        int row = idx >> 4;              // 0..127
        int c0 = q * 4;
        int m = m0 + row, b = m / SEQ, s = m % SEQ;
        int h = (n0 >> 6) + hh;

        float o1[4], o2[4];
        #pragma unroll
        for (int t = 0; t < 4; t++) {
            o1[t] = Ysh[row * YLD + hh * 64 + c0 + t]      + bias[hh * 64 + n0 + c0 + t];
            o2[t] = Ysh[row * YLD + hh * 64 + c0 + DH + t] + bias[hh * 64 + n0 + c0 + DH + t];
        }
        if (which != 2) {
            #pragma unroll
            for (int t = 0; t < 4; t++) {
                float sn = g_sin[s * DH + c0 + t], cs = g_cos[s * DH + c0 + t];
                float a = o1[t], bb = o2[t];
                o1[t] = a * cs - bb * sn;
                o2[t] = a * sn + bb * cs;
            }
        }
        size_t base = ((size_t)(b * NH + h) * SEQ + s) * HD;
        #pragma unroll
        for (int half_i = 0; half_i < 2; half_i++) {
            float* o = half_i ? o2 : o1;
            size_t off = base + c0 + half_i * DH;
            __half2 v0, v1;
            v0.x = __float2half(o[0]); v0.y = __float2half(o[1]);
            v1.x = __float2half(o[2]); v1.y = __float2half(o[3]);
            *(__half2*)(dstp + off)     = v0;
            *(__half2*)(dstp + off + 2) = v1;
        }
    }
}

// ---------------------------------------------------------------------------
// WMMA flash attention: 128q x 64k tiles, 8 warps (4m x 2n), 256 threads.
// QK^T + P.V: single fp16 MMAs. cp.async double-buffered K/V prefetch.
// Unnormalized exp + running row-sum; divide at the end. No smem overlays.
// ---------------------------------------------------------------------------
#define TQ 128
#define NT (SEQ / 64)
#define ALD 72      // fp16 smem ld
#define SLD 68      // fp32 smem ld
#define OFF_QH 0
#define OFF_K0 (OFF_QH + TQ*ALD*2)         // 18432
#define OFF_K1 (OFF_K0 + 64*ALD*2)         // 27648
#define OFF_V0 (OFF_K1 + 64*ALD*2)         // 36864
#define OFF_V1 (OFF_V0 + 64*ALD*2)         // 46080
#define OFF_PH (OFF_V1 + 64*ALD*2)         // 55296
#define OFF_S  (OFF_PH + TQ*ALD*2)         // 73728
#define OFF_L  (OFF_S + TQ*SLD*4)          // 108544
#define ATTN_SMEM (OFF_L + TQ*4)           // 109056

__global__ __launch_bounds__(256) void attn_wmma(float* __restrict__ out) {
    extern __shared__ __align__(128) char smraw[];
    __half* Qh_s = (__half*)(smraw + OFF_QH);
    __half* Ph_s = (__half*)(smraw + OFF_PH);
    float* Ssh = (float*)(smraw + OFF_S);
    float* Lsh = (float*)(smraw + OFF_L);

    int tid = threadIdx.x, wid = tid >> 5;
    int q0 = blockIdx.x * TQ, bh = blockIdx.y;
    int b = bh >> 4, h = bh & 15;

    const __half* Qp = g_Qh + ((size_t)bh * SEQ + q0) * HD;
    const __half* Kp = g_Kh + (size_t)bh * SEQ * HD;
    const __half* Vp = g_Vh + (size_t)bh * SEQ * HD;

    // load Q tile (128 rows x 64 cols fp16)
    #pragma unroll
    for (int i = 0; i < 4; i++) {
        int idx = tid + i * 256;         // 0..1023
        int row = idx >> 3, c8 = (idx & 7) * 8;
        *(uint4*)&Qh_s[row * ALD + c8] = *(const uint4*)&Qp[row * HD + c8];
    }
    if (tid < TQ) Lsh[tid] = 0.f;

    // prefetch tile 0 K/V
    {
        int row = tid >> 3, c8 = (tid & 7) * 8;
        size_t g = (size_t)row * HD + c8;       // kt=0
        uint32_t kd = (uint32_t)__cvta_generic_to_shared(smraw + OFF_K0) + (row * ALD + c8) * 2;
        uint32_t vd = (uint32_t)__cvta_generic_to_shared(smraw + OFF_V0) + (row * ALD + c8) * 2;
        CP_ASYNC16(kd, &Kp[g]);
        CP_ASYNC16(vd, &Vp[g]);
        int row2 = row + 32;
        size_t g2 = (size_t)row2 * HD + c8;
        uint32_t kd2 = (uint32_t)__cvta_generic_to_shared(smraw + OFF_K0) + (row2 * ALD + c8) * 2;
        uint32_t vd2 = (uint32_t)__cvta_generic_to_shared(smraw + OFF_V0) + (row2 * ALD + c8) * 2;
        CP_ASYNC16(kd2, &Kp[g2]);
        CP_ASYNC16(vd2, &Vp[g2]);
        CP_COMMIT();
    }

    int wm = (wid >> 1) * 32, wn = (wid & 1) * 32;
    wmma::fragment<wmma::accumulator, 16, 16, 16, float> ctx[2][2];
    #pragma unroll
    for (int i = 0; i < 2; i++)
        #pragma unroll
        for (int j = 0; j < 2; j++) wmma::fill_fragment(ctx[i][j], 0.f);

    for (int kt = 0; kt < NT; kt++) {
        int cur = kt & 1;
        __half* Kc = (__half*)(smraw + (cur ? OFF_K1 : OFF_K0));
        __half* Vc = (__half*)(smraw + (cur ? OFF_V1 : OFF_V0));

        CP_WAIT0();
        __syncthreads();   // K/V[cur] ready for all; buffers from kt-1 free

        if (kt + 1 < NT) {
            int nxt = 1 - cur;
            uint32_t kb = (uint32_t)__cvta_generic_to_shared(smraw + (nxt ? OFF_K1 : OFF_K0));
            uint32_t vb = (uint32_t)__cvta_generic_to_shared(smraw + (nxt ? OFF_V1 : OFF_V0));
            int row = tid >> 3, c8 = (tid & 7) * 8;
            #pragma unroll
            for (int half_i = 0; half_i < 2; half_i++) {
                int r = row + half_i * 32;
                size_t g = (size_t)((kt + 1) * 64 + r) * HD + c8;
                CP_ASYNC16(kb + (r * ALD + c8) * 2, &Kp[g]);
                CP_ASYNC16(vb + (r * ALD + c8) * 2, &Vp[g]);
            }
            CP_COMMIT();
        }

        // S = Q . K^T  (single fp16 MMA)
        wmma::fragment<wmma::accumulator, 16, 16, 16, float> sc[2][2];
        #pragma unroll
        for (int i = 0; i < 2; i++)
            #pragma unroll
            for (int j = 0; j < 2; j++) wmma::fill_fragment(sc[i][j], 0.f);
        #pragma unroll
        for (int ks = 0; ks < 4; ks++) {
            wmma::fragment<wmma::matrix_a, 16, 16, 16, __half, wmma::row_major> af[2];
            wmma::fragment<wmma::matrix_b, 16, 16, 16, __half, wmma::col_major> bf[2];
            #pragma unroll
            for (int i = 0; i < 2; i++)
                wmma::load_matrix_sync(af[i], &Qh_s[(wm + 16 * i) * ALD + 16 * ks], ALD);
            #pragma unroll
            for (int j = 0; j < 2; j++)
                wmma::load_matrix_sync(bf[j], &Kc[(wn + 16 * j) * ALD + 16 * ks], ALD);
            #pragma unroll
            for (int i = 0; i < 2; i++)
                #pragma unroll
                for (int j = 0; j < 2; j++)
                    wmma::mma_sync(sc[i][j], af[i], bf[j], sc[i][j]);
        }
        #pragma unroll
        for (int i = 0; i < 2; i++)
            #pragma unroll
            for (int j = 0; j < 2; j++)
                wmma::store_matrix_sync(&Ssh[(wm + 16 * i) * SLD + wn + 16 * j],
                                        sc[i][j], SLD, wmma::mem_row_major);
        __syncthreads();

        // exp (unnormalized) + row sums; P as fp16
        {
            int r = tid >> 1, c0 = (tid & 1) * 32;
            float sum = 0.f;
            #pragma unroll
            for (int cc = 0; cc < 32; cc += 2) {
                float p0 = expf(Ssh[r * SLD + c0 + cc]     * SCALE);
                float p1 = expf(Ssh[r * SLD + c0 + cc + 1] * SCALE);
                sum += p0 + p1;
                __half2 pv;
                pv.x = __float2half(p0);
                pv.y = __float2half(p1);
                *(__half2*)&Ph_s[r * ALD + c0 + cc] = pv;
            }
            sum += __shfl_xor_sync(0xffffffffu, sum, 1);
            if ((tid & 1) == 0) Lsh[r] += sum;
        }
        __syncthreads();

        // ctx += P . V  (single fp16 MMA)
        #pragma unroll
        for (int ks = 0; ks < 4; ks++) {
            wmma::fragment<wmma::matrix_a, 16, 16, 16, __half, wmma::row_major> af[2];
            wmma::fragment<wmma::matrix_b, 16, 16, 16, __half, wmma::row_major> bf[2];
            #pragma unroll
            for (int i = 0; i < 2; i++)
                wmma::load_matrix_sync(af[i], &Ph_s[(wm + 16 * i) * ALD + 16 * ks], ALD);
            #pragma unroll
            for (int j = 0; j < 2; j++)
                wmma::load_matrix_sync(bf[j], &Vc[16 * ks * ALD + wn + 16 * j], ALD);
            #pragma unroll
            for (int i = 0; i < 2; i++)
                #pragma unroll
                for (int j = 0; j < 2; j++)
                    wmma::mma_sync(ctx[i][j], af[i], bf[j], ctx[i][j]);
        }
    }
    __syncthreads();
    #pragma unroll
    for (int i = 0; i < 2; i++)
        #pragma unroll
        for (int j = 0; j < 2; j++)
            wmma::store_matrix_sync(&Ssh[(wm + 16 * i) * SLD + wn + 16 * j],
                                    ctx[i][j], SLD, wmma::mem_row_major);
    __syncthreads();

    {
        int r = tid >> 1, c0 = (tid & 1) * 32;
        float linv = 1.f / Lsh[r];
        int s = q0 + r;
        float* dst = out + ((size_t)b * SEQ + s) * DIM + h * HD + c0;
        #pragma unroll
        for (int cc = 0; cc < 32; cc += 4) {
            float4 v;
            v.x = Ssh[r * SLD + c0 + cc]     * linv;
            v.y = Ssh[r * SLD + c0 + cc + 1] * linv;
            v.z = Ssh[r * SLD + c0 + cc + 2] * linv;
            v.w = Ssh[r * SLD + c0 + cc + 3] * linv;
            *(float4*)(dst + cc) = v;
        }
    }
}

// ---------------------------------------------------------------------------
extern "C" void kernel_launch(void* const* d_in, const int* in_sizes, int n_in,
                              void* d_out, int out_size) {
    const float* X  = (const float*)d_in[0];
    const float* Wq = (const float*)d_in[1];
    const float* bq = (const float*)d_in[2];
    const float* Wk = (const float*)d_in[3];
    const float* bk = (const float*)d_in[4];
    const float* Wv = (const float*)d_in[5];
    const float* bv = (const float*)d_in[6];
    float* out = (float*)d_out;

    rope_table_kernel<<<(SEQ * DH + 255) / 256, 256>>>();

    split_kernel<<<(MTOT * DIM / 2 + 255) / 256, 256>>>(X, 0, MTOT * DIM / 2);
    split_kernel<<<(DIM * DIM / 2 + 255) / 256, 256>>>(Wq, 1, DIM * DIM / 2);
    split_kernel<<<(DIM * DIM / 2 + 255) / 256, 256>>>(Wk, 2, DIM * DIM / 2);
    split_kernel<<<(DIM * DIM / 2 + 255) / 256, 256>>>(Wv, 3, DIM * DIM / 2);

    cudaFuncSetAttribute(gemm_fused, cudaFuncAttributeMaxDynamicSharedMemorySize, PROJ_SMEM);
    dim3 ggrid(DIM / 128, MTOT / 128, 3);
    gemm_fused<<<ggrid, 256, PROJ_SMEM>>>(bq, bk, bv);

    cudaFuncSetAttribute(attn_wmma, cudaFuncAttributeMaxDynamicSharedMemorySize, ATTN_SMEM);
    dim3 agrid(SEQ / TQ, BATCH * NH);
    attn_wmma<<<agrid, 256, ATTN_SMEM>>>(out);
}